// round 8
// baseline (speedup 1.0000x reference)
#include <cuda_runtime.h>
#include <cstdint>

#define NN    50000
#define NE    800000
#define HD    64
#define MH    128
#define MHP   132    // padded stride (mod 32 == 4 -> conflict-free A-frags)
#define ET    64     // edge tile

// scratch
__device__ float g_agg[(size_t)NN * HD];
__device__ float g_Pcat[(size_t)NN * 256];   // [ h@W_src | h@W_dst + eb1 ]

__device__ __forceinline__ float f2tf(float f) {
    uint32_t u;
    asm("cvt.rna.tf32.f32 %0, %1;" : "=r"(u) : "f"(f));
    return __uint_as_float(u);
}

__device__ __forceinline__ void mma_tf32(float c[4], const uint32_t a[4],
                                         uint32_t b0, uint32_t b1) {
    asm volatile(
        "mma.sync.aligned.m16n8k8.row.col.f32.tf32.tf32.f32 "
        "{%0,%1,%2,%3},{%4,%5,%6,%7},{%8,%9},{%0,%1,%2,%3};"
        : "+f"(c[0]), "+f"(c[1]), "+f"(c[2]), "+f"(c[3])
        : "r"(a[0]), "r"(a[1]), "r"(a[2]), "r"(a[3]), "r"(b0), "r"(b1));
}

// ---------------------------------------------------------------------------
// prep: Pcat[n, 0:128]   = h[n] @ W_src
//       Pcat[n, 128:256] = h[n] @ W_dst + eb1        (bias folded here)
// Also zeroes g_agg rows. 64 nodes/block, 256 threads, 2 CTAs/SM.
// ---------------------------------------------------------------------------
__global__ __launch_bounds__(256, 2)
void prep_kernel(const float* __restrict__ h, const float* __restrict__ eW1,
                 const float* __restrict__ eb1)
{
    extern __shared__ float sm[];
    float* sW = sm;             // 64 x 256, col-swizzled
    float* sA = sW + 64 * 256;  // 64 x 68

    const int tid  = threadIdx.x;
    const int lane = tid & 31;
    const int w    = tid >> 5;
    const int lq   = lane >> 2;
    const int lr   = lane & 3;
    const int n0g  = blockIdx.x * 64;

    // zero this block's g_agg rows (64 rows x 16 float4)
    for (int i = tid; i < 64 * 16; i += 256) {
        int r = i >> 4, c4 = i & 15;
        int node = n0g + r;
        if (node < NN)
            reinterpret_cast<float4*>(g_agg)[(size_t)node * 16 + c4] =
                make_float4(0.f, 0.f, 0.f, 0.f);
    }

    for (int i = tid; i < 64 * 256; i += 256) {
        int k = i >> 8, c = i & 255;
        float v = (c < MH) ? eW1[k * MH + c] : eW1[(64 + k) * MH + (c - MH)];
        sW[k * 256 + (c ^ ((k & 3) << 3))] = f2tf(v);
    }
    for (int i = tid; i < 64 * 64; i += 256) {
        int r = i >> 6, c = i & 63;
        int node = min(n0g + r, NN - 1);
        sA[r * 68 + c] = f2tf(h[(size_t)node * HD + c]);
    }
    __syncthreads();

    const int mh = w >> 2, nc = w & 3;   // 2 (m32) x 4 (n64)

    float acc[2][8][4];
    #pragma unroll
    for (int i = 0; i < 2; i++)
        #pragma unroll
        for (int j = 0; j < 8; j++)
            #pragma unroll
            for (int q = 0; q < 4; q++) acc[i][j][q] = 0.f;

    for (int k = 0; k < 64; k += 8) {
        uint32_t a[2][4];
        #pragma unroll
        for (int i = 0; i < 2; i++) {
            int row = mh * 32 + 16 * i + lq;
            a[i][0] = __float_as_uint(sA[row * 68 + k + lr]);
            a[i][1] = __float_as_uint(sA[(row + 8) * 68 + k + lr]);
            a[i][2] = __float_as_uint(sA[row * 68 + k + 4 + lr]);
            a[i][3] = __float_as_uint(sA[(row + 8) * 68 + k + 4 + lr]);
        }
        #pragma unroll
        for (int j = 0; j < 8; j++) {
            int n0 = nc * 64 + 8 * j;
            int cs = (n0 + lq) ^ (lr << 3);
            uint32_t b0 = __float_as_uint(sW[(k + lr) * 256 + cs]);
            uint32_t b1 = __float_as_uint(sW[(k + 4 + lr) * 256 + cs]);
            mma_tf32(acc[0][j], a[0], b0, b1);
            mma_tf32(acc[1][j], a[1], b0, b1);
        }
    }

    #pragma unroll
    for (int i = 0; i < 2; i++) {
        int r0 = mh * 32 + 16 * i + lq;
        int g0 = n0g + r0, g1 = g0 + 8;
        #pragma unroll
        for (int j = 0; j < 8; j++) {
            int col = nc * 64 + 8 * j + 2 * lr;
            float bx = 0.f, by = 0.f;
            if (col >= MH) {             // dst half: fold eb1
                bx = eb1[col - MH];
                by = eb1[col - MH + 1];
            }
            if (g0 < NN)
                *(float2*)&g_Pcat[(size_t)g0 * 256 + col] =
                    make_float2(acc[i][j][0] + bx, acc[i][j][1] + by);
            if (g1 < NN)
                *(float2*)&g_Pcat[(size_t)g1 * 256 + col] =
                    make_float2(acc[i][j][2] + bx, acc[i][j][3] + by);
        }
    }
}

// ---------------------------------------------------------------------------
// Edge kernel: 64-edge tiles, 256 threads, 3 CTAs/SM, next-tile reg prefetch,
// lane-paired red.v4 scatter. eb1 is pre-folded into Pcat.
// ---------------------------------------------------------------------------
__global__ __launch_bounds__(256, 3)
void edge_kernel(const int* __restrict__ ei,
                 const float* __restrict__ ea,
                 const float* __restrict__ eW1,
                 const float* __restrict__ eW2, const float* __restrict__ eb2)
{
    extern __shared__ float sm[];
    float* sWea = sm;                     // 8 x 128, col-swizzled
    float* sW2  = sWea + 8 * MH;          // 128 x 64, col-swizzled
    float* sEA  = sW2 + MH * HD;          // 64 x 12
    float* sH   = sEA + ET * 12;          // 64 x 132
    int*   sSrc = (int*)(sH + ET * MHP);  // 64
    int*   sDst = sSrc + ET;              // 64

    const int tid  = threadIdx.x;
    const int lane = tid & 31;
    const int w    = tid >> 5;
    const int lq   = lane >> 2;
    const int lr   = lane & 3;

    for (int i = tid; i < 8 * MH; i += 256) {
        int k = i >> 7, c = i & 127;
        sWea[k * MH + (c ^ ((k & 3) << 3))] = f2tf(eW1[(2 * HD + k) * MH + c]);
    }
    for (int i = tid; i < MH * HD; i += 256) {
        int r = i >> 6, n = i & 63;
        sW2[r * HD + (n ^ ((r & 3) << 3))] = f2tf(eW2[i]);
    }

    const int mh = w >> 2;   // 0..1 -> m32
    const int nq = w & 3;    // 0..3 -> n32 (phase1) / n16 (phase2)

    float2 b2p[2];
    #pragma unroll
    for (int j = 0; j < 2; j++) b2p[j] = *(const float2*)&eb2[nq * 16 + 8 * j + 2 * lr];

    const int numTiles = NE / ET;   // 12500

    // prefetch first tile
    int pS = 0, pD = 0;
    float2 pEA = make_float2(0.f, 0.f);
    int t = blockIdx.x;
    if (t < numTiles) {
        const int e0 = t * ET;
        if (tid < ET) { pS = ei[e0 + tid]; pD = ei[NE + e0 + tid]; }
        pEA = *(const float2*)&ea[(size_t)e0 * 8 + 2 * tid];
    }

    for (; t < numTiles; t += gridDim.x) {
        __syncthreads();

        if (tid < ET) {
            sSrc[tid] = min(max(pS, 0), NN - 1);
            sDst[tid] = min(max(pD, 0), NN - 1);
        }
        {
            int idx = 2 * tid;
            int r = idx >> 3, c = idx & 7;
            sEA[r * 12 + c]     = f2tf(pEA.x);
            sEA[r * 12 + c + 1] = f2tf(pEA.y);
        }
        __syncthreads();

        int tn = t + gridDim.x;
        if (tn < numTiles) {
            const int en = tn * ET;
            if (tid < ET) { pS = ei[en + tid]; pD = ei[NE + en + tid]; }
            pEA = *(const float2*)&ea[(size_t)en * 8 + 2 * tid];
        }

        // ---- phase 1: [64,8] @ [8,128] ----
        float c1[2][4][4];
        #pragma unroll
        for (int i = 0; i < 2; i++)
            #pragma unroll
            for (int j = 0; j < 4; j++)
                #pragma unroll
                for (int q = 0; q < 4; q++) c1[i][j][q] = 0.f;

        {
            uint32_t a[2][4];
            #pragma unroll
            for (int i = 0; i < 2; i++) {
                int row = mh * 32 + 16 * i + lq;
                a[i][0] = __float_as_uint(sEA[row * 12 + lr]);
                a[i][1] = __float_as_uint(sEA[(row + 8) * 12 + lr]);
                a[i][2] = __float_as_uint(sEA[row * 12 + 4 + lr]);
                a[i][3] = __float_as_uint(sEA[(row + 8) * 12 + 4 + lr]);
            }
            #pragma unroll
            for (int j = 0; j < 4; j++) {
                int n0 = nq * 32 + 8 * j;
                int cs = (n0 + lq) ^ (lr << 3);
                uint32_t b0 = __float_as_uint(sWea[lr * MH + cs]);
                uint32_t b1 = __float_as_uint(sWea[(4 + lr) * MH + cs]);
                mma_tf32(c1[0][j], a[0], b0, b1);
                mma_tf32(c1[1][j], a[1], b0, b1);
            }
        }

        // gathered Pcat (bias pre-folded), relu -> sH
        #pragma unroll
        for (int i = 0; i < 2; i++) {
            int r0 = mh * 32 + 16 * i + lq;
            int r1 = r0 + 8;
            const float* ps0 = g_Pcat + (size_t)sSrc[r0] * 256;
            const float* pd0 = g_Pcat + (size_t)sDst[r0] * 256 + MH;
            const float* ps1 = g_Pcat + (size_t)sSrc[r1] * 256;
            const float* pd1 = g_Pcat + (size_t)sDst[r1] * 256 + MH;
            #pragma unroll
            for (int j = 0; j < 4; j++) {
                int col = nq * 32 + 8 * j + 2 * lr;
                float2 s0 = *(const float2*)&ps0[col];
                float2 d0 = *(const float2*)&pd0[col];
                float2 s1 = *(const float2*)&ps1[col];
                float2 d1 = *(const float2*)&pd1[col];
                uint2 v0, v1;
                v0.x = __float_as_uint(f2tf(fmaxf(c1[i][j][0] + s0.x + d0.x, 0.f)));
                v0.y = __float_as_uint(f2tf(fmaxf(c1[i][j][1] + s0.y + d0.y, 0.f)));
                v1.x = __float_as_uint(f2tf(fmaxf(c1[i][j][2] + s1.x + d1.x, 0.f)));
                v1.y = __float_as_uint(f2tf(fmaxf(c1[i][j][3] + s1.y + d1.y, 0.f)));
                *(uint2*)&sH[r0 * MHP + col] = v0;
                *(uint2*)&sH[r1 * MHP + col] = v1;
            }
        }
        __syncthreads();

        // ---- phase 2: [64,128] @ [128,64] ----
        float c2[2][2][4];
        #pragma unroll
        for (int i = 0; i < 2; i++)
            #pragma unroll
            for (int j = 0; j < 2; j++)
                #pragma unroll
                for (int q = 0; q < 4; q++) c2[i][j][q] = 0.f;

        for (int k = 0; k < MH; k += 8) {
            uint32_t a[2][4];
            #pragma unroll
            for (int i = 0; i < 2; i++) {
                int row = mh * 32 + 16 * i + lq;
                a[i][0] = __float_as_uint(sH[row * MHP + k + lr]);
                a[i][1] = __float_as_uint(sH[(row + 8) * MHP + k + lr]);
                a[i][2] = __float_as_uint(sH[row * MHP + k + 4 + lr]);
                a[i][3] = __float_as_uint(sH[(row + 8) * MHP + k + 4 + lr]);
            }
            #pragma unroll
            for (int j = 0; j < 2; j++) {
                int n0 = nq * 16 + 8 * j;
                int cs = (n0 + lq) ^ (lr << 3);
                uint32_t b0 = __float_as_uint(sW2[(k + lr) * HD + cs]);
                uint32_t b1 = __float_as_uint(sW2[(k + 4 + lr) * HD + cs]);
                mma_tf32(c2[0][j], a[0], b0, b1);
                mma_tf32(c2[1][j], a[1], b0, b1);
            }
        }

        // scatter-add: pair lanes (lr, lr^1) -> red.v4 from even-lr lanes
        #pragma unroll
        for (int i = 0; i < 2; i++) {
            int r0 = mh * 32 + 16 * i + lq;
            int r1 = r0 + 8;
            int d0 = sDst[r0], d1 = sDst[r1];
            #pragma unroll
            for (int j = 0; j < 2; j++) {
                float u0 = c2[i][j][0] + b2p[j].x;
                float u1 = c2[i][j][1] + b2p[j].y;
                float u2 = c2[i][j][2] + b2p[j].x;
                float u3 = c2[i][j][3] + b2p[j].y;
                float w0 = __shfl_xor_sync(0xffffffffu, u0, 1);
                float w1 = __shfl_xor_sync(0xffffffffu, u1, 1);
                float w2 = __shfl_xor_sync(0xffffffffu, u2, 1);
                float w3 = __shfl_xor_sync(0xffffffffu, u3, 1);
                if (!(lr & 1)) {
                    int col = nq * 16 + 8 * j + (lr & 2) * 2;
                    float* p0 = g_agg + (size_t)d0 * HD + col;
                    float* p1 = g_agg + (size_t)d1 * HD + col;
                    asm volatile("red.global.add.v4.f32 [%0], {%1, %2, %3, %4};"
                                 :: "l"(p0), "f"(u0), "f"(u1), "f"(w0), "f"(w1)
                                 : "memory");
                    asm volatile("red.global.add.v4.f32 [%0], {%1, %2, %3, %4};"
                                 :: "l"(p1), "f"(u2), "f"(u3), "f"(w2), "f"(w3)
                                 : "memory");
                }
            }
        }
    }
}

// ---------------------------------------------------------------------------
// Node kernel: tf32 MMA, 64 nodes/tile, 256 threads, next-tile reg prefetch.
// ---------------------------------------------------------------------------
#define TILE 64
__global__ __launch_bounds__(256, 1)
void node_kernel(const float* __restrict__ h,
                 const float* __restrict__ nW1, const float* __restrict__ nb1,
                 const float* __restrict__ nW2, const float* __restrict__ nb2,
                 const float* __restrict__ lg,  const float* __restrict__ lb,
                 float* __restrict__ out)
{
    extern __shared__ float sm[];
    float* sW1 = sm;
    float* sW2 = sW1 + MH * MH;
    float* sU  = sW2 + MH * HD;
    float* sH  = sU  + TILE * MHP;
    float* sO  = sH  + TILE * MHP;
    float* sB1 = sO  + TILE * 65;
    float* sB2 = sB1 + MH;
    float* sG  = sB2 + HD;
    float* sB  = sG  + HD;
    float* sMu = sB  + HD;
    float* sRs = sMu + TILE;

    const int tid  = threadIdx.x;
    const int lane = tid & 31;
    const int w    = tid >> 5;
    const int lq   = lane >> 2;
    const int lr   = lane & 3;

    for (int i = tid; i < MH * MH; i += 256) {
        int r = i >> 7, n = i & 127;
        sW1[r * MH + (n ^ ((r & 3) << 3))] = f2tf(nW1[i]);
    }
    for (int i = tid; i < MH * HD; i += 256) {
        int r = i >> 6, n = i & 63;
        sW2[r * HD + (n ^ ((r & 3) << 3))] = f2tf(nW2[i]);
    }
    for (int i = tid; i < MH; i += 256) sB1[i] = nb1[i];
    if (tid < HD) { sB2[tid] = nb2[tid]; sG[tid] = lg[tid]; sB[tid] = lb[tid]; }
    __syncthreads();

    const int mh = w >> 2, nq = w & 3;
    const int mq = w & 3,  nh = w >> 2;

    float2 b1p[4], b2p[4];
    #pragma unroll
    for (int j = 0; j < 4; j++) {
        b1p[j] = *(const float2*)&sB1[nq * 32 + 8 * j + 2 * lr];
        b2p[j] = *(const float2*)&sB2[nh * 32 + 8 * j + 2 * lr];
    }

    const int numTiles = (NN + TILE - 1) / TILE;

    float pf[32];
    int t = blockIdx.x;
    if (t < numTiles) {
        const int n0g = t * TILE;
        #pragma unroll
        for (int v = 0; v < 32; v++) {
            int i = v * 256 + tid;
            int r = i >> 7, k = i & 127;
            int node = min(n0g + r, NN - 1);
            pf[v] = (k < HD) ? h[(size_t)node * HD + k]
                             : g_agg[(size_t)node * HD + (k - HD)];
        }
    }

    for (; t < numTiles; t += gridDim.x) {
        const int n0g = t * TILE;
        __syncthreads();

        #pragma unroll
        for (int v = 0; v < 32; v++) {
            int i = v * 256 + tid;
            int r = i >> 7, k = i & 127;
            sU[r * MHP + k] = f2tf(pf[v]);
        }
        __syncthreads();

        int tn = t + gridDim.x;
        if (tn < numTiles) {
            const int nn0 = tn * TILE;
            #pragma unroll
            for (int v = 0; v < 32; v++) {
                int i = v * 256 + tid;
                int r = i >> 7, k = i & 127;
                int node = min(nn0 + r, NN - 1);
                pf[v] = (k < HD) ? h[(size_t)node * HD + k]
                                 : g_agg[(size_t)node * HD + (k - HD)];
            }
        }

        float c1[2][4][4];
        #pragma unroll
        for (int i = 0; i < 2; i++)
            #pragma unroll
            for (int j = 0; j < 4; j++)
                #pragma unroll
                for (int q = 0; q < 4; q++) c1[i][j][q] = 0.f;

        for (int k = 0; k < MH; k += 8) {
            uint32_t a[2][4];
            #pragma unroll
            for (int i = 0; i < 2; i++) {
                int row = mh * 32 + 16 * i + lq;
                a[i][0] = __float_as_uint(sU[row * MHP + k + lr]);
                a[i][1] = __float_as_uint(sU[(row + 8) * MHP + k + lr]);
                a[i][2] = __float_as_uint(sU[row * MHP + k + 4 + lr]);
                a[i][3] = __float_as_uint(sU[(row + 8) * MHP + k + 4 + lr]);
            }
            #pragma unroll
            for (int j = 0; j < 4; j++) {
                int n0 = nq * 32 + 8 * j;
                int cs = (n0 + lq) ^ (lr << 3);
                uint32_t b0 = __float_as_uint(sW1[(k + lr) * MH + cs]);
                uint32_t b1 = __float_as_uint(sW1[(k + 4 + lr) * MH + cs]);
                mma_tf32(c1[0][j], a[0], b0, b1);
                mma_tf32(c1[1][j], a[1], b0, b1);
            }
        }

        #pragma unroll
        for (int i = 0; i < 2; i++) {
            #pragma unroll
            for (int j = 0; j < 4; j++) {
                int row = mh * 32 + 16 * i + lq;
                int col = nq * 32 + 8 * j + 2 * lr;
                uint2 v0, v1;
                v0.x = __float_as_uint(f2tf(fmaxf(c1[i][j][0] + b1p[j].x, 0.f)));
                v0.y = __float_as_uint(f2tf(fmaxf(c1[i][j][1] + b1p[j].y, 0.f)));
                v1.x = __float_as_uint(f2tf(fmaxf(c1[i][j][2] + b1p[j].x, 0.f)));
                v1.y = __float_as_uint(f2tf(fmaxf(c1[i][j][3] + b1p[j].y, 0.f)));
                *(uint2*)&sH[row * MHP + col]       = v0;
                *(uint2*)&sH[(row + 8) * MHP + col] = v1;
            }
        }
        __syncthreads();

        float c2[4][4];
        #pragma unroll
        for (int j = 0; j < 4; j++)
            #pragma unroll
            for (int q = 0; q < 4; q++) c2[j][q] = 0.f;

        const int m0 = mq * 16;
        for (int k = 0; k < MH; k += 8) {
            uint32_t a[4];
            int row = m0 + lq;
            a[0] = __float_as_uint(sH[row * MHP + k + lr]);
            a[1] = __float_as_uint(sH[(row + 8) * MHP + k + lr]);
            a[2] = __float_as_uint(sH[row * MHP + k + 4 + lr]);
            a[3] = __float_as_uint(sH[(row + 8) * MHP + k + 4 + lr]);
            #pragma unroll
            for (int j = 0; j < 4; j++) {
                int n0 = nh * 32 + 8 * j;
                int cs = (n0 + lq) ^ (lr << 3);
                uint32_t b0 = __float_as_uint(sW2[(k + lr) * HD + cs]);
                uint32_t b1 = __float_as_uint(sW2[(k + 4 + lr) * HD + cs]);
                mma_tf32(c2[j], a, b0, b1);
            }
        }

        {
            int r0 = m0 + lq;
            int r1 = r0 + 8;
            int g0 = n0g + r0, g1 = n0g + r1;
            #pragma unroll
            for (int j = 0; j < 4; j++) {
                int col = nh * 32 + 8 * j + 2 * lr;
                if (g0 < NN) {
                    float2 hv = *(const float2*)&h[(size_t)g0 * HD + col];
                    sO[r0 * 65 + col]     = c2[j][0] + b2p[j].x + hv.x;
                    sO[r0 * 65 + col + 1] = c2[j][1] + b2p[j].y + hv.y;
                }
                if (g1 < NN) {
                    float2 hv = *(const float2*)&h[(size_t)g1 * HD + col];
                    sO[r1 * 65 + col]     = c2[j][2] + b2p[j].x + hv.x;
                    sO[r1 * 65 + col + 1] = c2[j][3] + b2p[j].y + hv.y;
                }
            }
        }
        __syncthreads();

        if (tid < TILE) {
            float s = 0.f, s2 = 0.f;
            #pragma unroll 8
            for (int c = 0; c < HD; c++) {
                float v = sO[tid * 65 + c];
                s += v;
                s2 = fmaf(v, v, s2);
            }
            float mu  = s * (1.f / HD);
            float var = fmaxf(s2 * (1.f / HD) - mu * mu, 0.f);
            sMu[tid] = mu;
            sRs[tid] = rsqrtf(var + 1e-5f);
        }
        __syncthreads();

        for (int i = tid; i < TILE * HD; i += 256) {
            int r = i >> 6;
            int c = i & 63;
            int node = n0g + r;
            if (node < NN)
                out[(size_t)node * HD + c] =
                    (sO[r * 65 + c] - sMu[r]) * sRs[r] * sG[c] + sB[c];
        }
    }
}

// ---------------------------------------------------------------------------
extern "C" void kernel_launch(void* const* d_in, const int* in_sizes, int n_in,
                              void* d_out, int out_size)
{
    const float* h   = (const float*)d_in[0];
    const int*   ei  = (const int*)d_in[1];     // int32 (JAX default downcast)
    const float* ea  = (const float*)d_in[2];
    const float* eW1 = (const float*)d_in[3];
    const float* eb1 = (const float*)d_in[4];
    const float* eW2 = (const float*)d_in[5];
    const float* eb2 = (const float*)d_in[6];
    const float* nW1 = (const float*)d_in[7];
    const float* nb1 = (const float*)d_in[8];
    const float* nW2 = (const float*)d_in[9];
    const float* nb2 = (const float*)d_in[10];
    const float* lg  = (const float*)d_in[11];
    const float* lb  = (const float*)d_in[12];
    float*       out = (float*)d_out;

    const int smem_prep = (64 * 256 + 64 * 68) * 4;
    const int smem_edge = (8 * MH + MH * HD + ET * 12 + ET * MHP) * 4
                          + 2 * ET * 4;
    const int smem_node = (MH * MH + MH * HD + 2 * TILE * MHP + TILE * 65
                           + MH + 5 * HD + TILE) * 4;

    cudaFuncSetAttribute(prep_kernel, cudaFuncAttributeMaxDynamicSharedMemorySize, smem_prep);
    cudaFuncSetAttribute(edge_kernel, cudaFuncAttributeMaxDynamicSharedMemorySize, smem_edge);
    cudaFuncSetAttribute(node_kernel, cudaFuncAttributeMaxDynamicSharedMemorySize, smem_node);

    prep_kernel<<<(NN + 63) / 64, 256, smem_prep>>>(h, eW1, eb1);
    edge_kernel<<<444, 256, smem_edge>>>(ei, ea, eW1, eW2, eb2);
    node_kernel<<<148, 256, smem_node>>>(h, nW1, nb1, nW2, nb2, lg, lb, out);
}

// round 9
// speedup vs baseline: 1.0498x; 1.0498x over previous
#include <cuda_runtime.h>
#include <cstdint>

#define NN    50000
#define NE    800000
#define HD    64
#define MH    128
#define MHP   132    // padded stride (mod 32 == 4 -> conflict-free A-frags)
#define ET    64     // edge tile

// scratch
__device__ float g_agg[(size_t)NN * HD];
__device__ float g_Pcat[(size_t)NN * 256];   // [ h@W_src | h@W_dst + eb1 ]

__device__ __forceinline__ float f2tf(float f) {
    uint32_t u;
    asm("cvt.rna.tf32.f32 %0, %1;" : "=r"(u) : "f"(f));
    return __uint_as_float(u);
}

__device__ __forceinline__ void mma_tf32(float c[4], const uint32_t a[4],
                                         uint32_t b0, uint32_t b1) {
    asm volatile(
        "mma.sync.aligned.m16n8k8.row.col.f32.tf32.tf32.f32 "
        "{%0,%1,%2,%3},{%4,%5,%6,%7},{%8,%9},{%0,%1,%2,%3};"
        : "+f"(c[0]), "+f"(c[1]), "+f"(c[2]), "+f"(c[3])
        : "r"(a[0]), "r"(a[1]), "r"(a[2]), "r"(a[3]), "r"(b0), "r"(b1));
}

// ---------------------------------------------------------------------------
// prep (persistent): Pcat[n,0:128] = h@W_src ; Pcat[n,128:256] = h@W_dst + eb1
// Also zeroes g_agg rows. 148 blocks x 512 threads, weights loaded ONCE.
// ---------------------------------------------------------------------------
__global__ __launch_bounds__(512, 1)
void prep_kernel(const float* __restrict__ h, const float* __restrict__ eW1,
                 const float* __restrict__ eb1)
{
    extern __shared__ float sm[];
    float* sW = sm;             // 64 x 256, col-swizzled
    float* sA = sW + 64 * 256;  // 128 x 68

    const int tid  = threadIdx.x;
    const int lane = tid & 31;
    const int w    = tid >> 5;
    const int lq   = lane >> 2;
    const int lr   = lane & 3;

    // weights once per block
    for (int i = tid; i < 64 * 256; i += 512) {
        int k = i >> 8, c = i & 255;
        float v = (c < MH) ? eW1[k * MH + c] : eW1[(64 + k) * MH + (c - MH)];
        sW[k * 256 + (c ^ ((k & 3) << 3))] = f2tf(v);
    }

    const int mh = w >> 2, nc = w & 3;   // 4 (m32) x 4 (n64)
    const int numTiles = (NN + 127) / 128;   // 391

    for (int tile = blockIdx.x; tile < numTiles; tile += gridDim.x) {
        const int n0g = tile * 128;
        __syncthreads();   // sA free (also covers first-iter weight load)

        // zero this tile's g_agg rows
        for (int i = tid; i < 128 * 16; i += 512) {
            int r = i >> 4, c4 = i & 15;
            int node = n0g + r;
            if (node < NN)
                reinterpret_cast<float4*>(g_agg)[(size_t)node * 16 + c4] =
                    make_float4(0.f, 0.f, 0.f, 0.f);
        }
        // gather A tile
        for (int i = tid; i < 128 * 64; i += 512) {
            int r = i >> 6, c = i & 63;
            int node = min(n0g + r, NN - 1);
            sA[r * 68 + c] = f2tf(h[(size_t)node * HD + c]);
        }
        __syncthreads();

        float acc[2][8][4];
        #pragma unroll
        for (int i = 0; i < 2; i++)
            #pragma unroll
            for (int j = 0; j < 8; j++)
                #pragma unroll
                for (int q = 0; q < 4; q++) acc[i][j][q] = 0.f;

        for (int k = 0; k < 64; k += 8) {
            uint32_t a[2][4];
            #pragma unroll
            for (int i = 0; i < 2; i++) {
                int row = mh * 32 + 16 * i + lq;
                a[i][0] = __float_as_uint(sA[row * 68 + k + lr]);
                a[i][1] = __float_as_uint(sA[(row + 8) * 68 + k + lr]);
                a[i][2] = __float_as_uint(sA[row * 68 + k + 4 + lr]);
                a[i][3] = __float_as_uint(sA[(row + 8) * 68 + k + 4 + lr]);
            }
            #pragma unroll
            for (int j = 0; j < 8; j++) {
                int n0 = nc * 64 + 8 * j;
                int cs = (n0 + lq) ^ (lr << 3);
                uint32_t b0 = __float_as_uint(sW[(k + lr) * 256 + cs]);
                uint32_t b1 = __float_as_uint(sW[(k + 4 + lr) * 256 + cs]);
                mma_tf32(acc[0][j], a[0], b0, b1);
                mma_tf32(acc[1][j], a[1], b0, b1);
            }
        }

        #pragma unroll
        for (int i = 0; i < 2; i++) {
            int r0 = mh * 32 + 16 * i + lq;
            int g0 = n0g + r0, g1 = g0 + 8;
            #pragma unroll
            for (int j = 0; j < 8; j++) {
                int col = nc * 64 + 8 * j + 2 * lr;
                float bx = 0.f, by = 0.f;
                if (col >= MH) {             // dst half: fold eb1
                    bx = eb1[col - MH];
                    by = eb1[col - MH + 1];
                }
                if (g0 < NN)
                    *(float2*)&g_Pcat[(size_t)g0 * 256 + col] =
                        make_float2(acc[i][j][0] + bx, acc[i][j][1] + by);
                if (g1 < NN)
                    *(float2*)&g_Pcat[(size_t)g1 * 256 + col] =
                        make_float2(acc[i][j][2] + bx, acc[i][j][3] + by);
            }
        }
    }
}

// ---------------------------------------------------------------------------
// Edge kernel (R7 structure): 64-edge tiles, 256 threads, 2 CTAs/SM,
// next-tile reg prefetch, lane-paired red.v4 scatter. eb1 pre-folded in Pcat.
// ---------------------------------------------------------------------------
__global__ __launch_bounds__(256, 2)
void edge_kernel(const int* __restrict__ ei,
                 const float* __restrict__ ea,
                 const float* __restrict__ eW1,
                 const float* __restrict__ eW2, const float* __restrict__ eb2)
{
    extern __shared__ float sm[];
    float* sWea = sm;                     // 8 x 128, col-swizzled
    float* sW2  = sWea + 8 * MH;          // 128 x 64, col-swizzled
    float* sEA  = sW2 + MH * HD;          // 64 x 12
    float* sH   = sEA + ET * 12;          // 64 x 132
    int*   sSrc = (int*)(sH + ET * MHP);  // 64
    int*   sDst = sSrc + ET;              // 64

    const int tid  = threadIdx.x;
    const int lane = tid & 31;
    const int w    = tid >> 5;
    const int lq   = lane >> 2;
    const int lr   = lane & 3;

    for (int i = tid; i < 8 * MH; i += 256) {
        int k = i >> 7, c = i & 127;
        sWea[k * MH + (c ^ ((k & 3) << 3))] = f2tf(eW1[(2 * HD + k) * MH + c]);
    }
    for (int i = tid; i < MH * HD; i += 256) {
        int r = i >> 6, n = i & 63;
        sW2[r * HD + (n ^ ((r & 3) << 3))] = f2tf(eW2[i]);
    }

    const int mh = w >> 2;   // 0..1 -> m32
    const int nq = w & 3;    // 0..3 -> n32 (phase1) / n16 (phase2)

    float2 b2p[2];
    #pragma unroll
    for (int j = 0; j < 2; j++) b2p[j] = *(const float2*)&eb2[nq * 16 + 8 * j + 2 * lr];

    const int numTiles = NE / ET;   // 12500

    // prefetch first tile
    int pS = 0, pD = 0;
    float2 pEA = make_float2(0.f, 0.f);
    int t = blockIdx.x;
    if (t < numTiles) {
        const int e0 = t * ET;
        if (tid < ET) { pS = ei[e0 + tid]; pD = ei[NE + e0 + tid]; }
        pEA = *(const float2*)&ea[(size_t)e0 * 8 + 2 * tid];
    }

    for (; t < numTiles; t += gridDim.x) {
        __syncthreads();

        if (tid < ET) {
            sSrc[tid] = min(max(pS, 0), NN - 1);
            sDst[tid] = min(max(pD, 0), NN - 1);
        }
        {
            int idx = 2 * tid;
            int r = idx >> 3, c = idx & 7;
            sEA[r * 12 + c]     = f2tf(pEA.x);
            sEA[r * 12 + c + 1] = f2tf(pEA.y);
        }
        __syncthreads();

        int tn = t + gridDim.x;
        if (tn < numTiles) {
            const int en = tn * ET;
            if (tid < ET) { pS = ei[en + tid]; pD = ei[NE + en + tid]; }
            pEA = *(const float2*)&ea[(size_t)en * 8 + 2 * tid];
        }

        // ---- phase 1: [64,8] @ [8,128] ----
        float c1[2][4][4];
        #pragma unroll
        for (int i = 0; i < 2; i++)
            #pragma unroll
            for (int j = 0; j < 4; j++)
                #pragma unroll
                for (int q = 0; q < 4; q++) c1[i][j][q] = 0.f;

        {
            uint32_t a[2][4];
            #pragma unroll
            for (int i = 0; i < 2; i++) {
                int row = mh * 32 + 16 * i + lq;
                a[i][0] = __float_as_uint(sEA[row * 12 + lr]);
                a[i][1] = __float_as_uint(sEA[(row + 8) * 12 + lr]);
                a[i][2] = __float_as_uint(sEA[row * 12 + 4 + lr]);
                a[i][3] = __float_as_uint(sEA[(row + 8) * 12 + 4 + lr]);
            }
            #pragma unroll
            for (int j = 0; j < 4; j++) {
                int n0 = nq * 32 + 8 * j;
                int cs = (n0 + lq) ^ (lr << 3);
                uint32_t b0 = __float_as_uint(sWea[lr * MH + cs]);
                uint32_t b1 = __float_as_uint(sWea[(4 + lr) * MH + cs]);
                mma_tf32(c1[0][j], a[0], b0, b1);
                mma_tf32(c1[1][j], a[1], b0, b1);
            }
        }

        // gathered Pcat (bias pre-folded), relu -> sH
        #pragma unroll
        for (int i = 0; i < 2; i++) {
            int r0 = mh * 32 + 16 * i + lq;
            int r1 = r0 + 8;
            const float* ps0 = g_Pcat + (size_t)sSrc[r0] * 256;
            const float* pd0 = g_Pcat + (size_t)sDst[r0] * 256 + MH;
            const float* ps1 = g_Pcat + (size_t)sSrc[r1] * 256;
            const float* pd1 = g_Pcat + (size_t)sDst[r1] * 256 + MH;
            #pragma unroll
            for (int j = 0; j < 4; j++) {
                int col = nq * 32 + 8 * j + 2 * lr;
                float2 s0 = *(const float2*)&ps0[col];
                float2 d0 = *(const float2*)&pd0[col];
                float2 s1 = *(const float2*)&ps1[col];
                float2 d1 = *(const float2*)&pd1[col];
                uint2 v0, v1;
                v0.x = __float_as_uint(f2tf(fmaxf(c1[i][j][0] + s0.x + d0.x, 0.f)));
                v0.y = __float_as_uint(f2tf(fmaxf(c1[i][j][1] + s0.y + d0.y, 0.f)));
                v1.x = __float_as_uint(f2tf(fmaxf(c1[i][j][2] + s1.x + d1.x, 0.f)));
                v1.y = __float_as_uint(f2tf(fmaxf(c1[i][j][3] + s1.y + d1.y, 0.f)));
                *(uint2*)&sH[r0 * MHP + col] = v0;
                *(uint2*)&sH[r1 * MHP + col] = v1;
            }
        }
        __syncthreads();

        // ---- phase 2: [64,128] @ [128,64] ----
        float c2[2][2][4];
        #pragma unroll
        for (int i = 0; i < 2; i++)
            #pragma unroll
            for (int j = 0; j < 2; j++)
                #pragma unroll
                for (int q = 0; q < 4; q++) c2[i][j][q] = 0.f;

        for (int k = 0; k < MH; k += 8) {
            uint32_t a[2][4];
            #pragma unroll
            for (int i = 0; i < 2; i++) {
                int row = mh * 32 + 16 * i + lq;
                a[i][0] = __float_as_uint(sH[row * MHP + k + lr]);
                a[i][1] = __float_as_uint(sH[(row + 8) * MHP + k + lr]);
                a[i][2] = __float_as_uint(sH[row * MHP + k + 4 + lr]);
                a[i][3] = __float_as_uint(sH[(row + 8) * MHP + k + 4 + lr]);
            }
            #pragma unroll
            for (int j = 0; j < 2; j++) {
                int n0 = nq * 16 + 8 * j;
                int cs = (n0 + lq) ^ (lr << 3);
                uint32_t b0 = __float_as_uint(sW2[(k + lr) * HD + cs]);
                uint32_t b1 = __float_as_uint(sW2[(k + 4 + lr) * HD + cs]);
                mma_tf32(c2[0][j], a[0], b0, b1);
                mma_tf32(c2[1][j], a[1], b0, b1);
            }
        }

        // scatter-add: pair lanes (lr, lr^1) -> red.v4 from even-lr lanes
        #pragma unroll
        for (int i = 0; i < 2; i++) {
            int r0 = mh * 32 + 16 * i + lq;
            int r1 = r0 + 8;
            int d0 = sDst[r0], d1 = sDst[r1];
            #pragma unroll
            for (int j = 0; j < 2; j++) {
                float u0 = c2[i][j][0] + b2p[j].x;
                float u1 = c2[i][j][1] + b2p[j].y;
                float u2 = c2[i][j][2] + b2p[j].x;
                float u3 = c2[i][j][3] + b2p[j].y;
                float w0 = __shfl_xor_sync(0xffffffffu, u0, 1);
                float w1 = __shfl_xor_sync(0xffffffffu, u1, 1);
                float w2 = __shfl_xor_sync(0xffffffffu, u2, 1);
                float w3 = __shfl_xor_sync(0xffffffffu, u3, 1);
                if (!(lr & 1)) {
                    int col = nq * 16 + 8 * j + (lr & 2) * 2;
                    float* p0 = g_agg + (size_t)d0 * HD + col;
                    float* p1 = g_agg + (size_t)d1 * HD + col;
                    asm volatile("red.global.add.v4.f32 [%0], {%1, %2, %3, %4};"
                                 :: "l"(p0), "f"(u0), "f"(u1), "f"(w0), "f"(w1)
                                 : "memory");
                    asm volatile("red.global.add.v4.f32 [%0], {%1, %2, %3, %4};"
                                 :: "l"(p1), "f"(u2), "f"(u3), "f"(w2), "f"(w3)
                                 : "memory");
                }
            }
        }
    }
}

// ---------------------------------------------------------------------------
// Node kernel: tf32 MMA, 64 nodes/tile, 256 threads, next-tile reg prefetch.
// ---------------------------------------------------------------------------
#define TILE 64
__global__ __launch_bounds__(256, 1)
void node_kernel(const float* __restrict__ h,
                 const float* __restrict__ nW1, const float* __restrict__ nb1,
                 const float* __restrict__ nW2, const float* __restrict__ nb2,
                 const float* __restrict__ lg,  const float* __restrict__ lb,
                 float* __restrict__ out)
{
    extern __shared__ float sm[];
    float* sW1 = sm;
    float* sW2 = sW1 + MH * MH;
    float* sU  = sW2 + MH * HD;
    float* sH  = sU  + TILE * MHP;
    float* sO  = sH  + TILE * MHP;
    float* sB1 = sO  + TILE * 65;
    float* sB2 = sB1 + MH;
    float* sG  = sB2 + HD;
    float* sB  = sG  + HD;
    float* sMu = sB  + HD;
    float* sRs = sMu + TILE;

    const int tid  = threadIdx.x;
    const int lane = tid & 31;
    const int w    = tid >> 5;
    const int lq   = lane >> 2;
    const int lr   = lane & 3;

    for (int i = tid; i < MH * MH; i += 256) {
        int r = i >> 7, n = i & 127;
        sW1[r * MH + (n ^ ((r & 3) << 3))] = f2tf(nW1[i]);
    }
    for (int i = tid; i < MH * HD; i += 256) {
        int r = i >> 6, n = i & 63;
        sW2[r * HD + (n ^ ((r & 3) << 3))] = f2tf(nW2[i]);
    }
    for (int i = tid; i < MH; i += 256) sB1[i] = nb1[i];
    if (tid < HD) { sB2[tid] = nb2[tid]; sG[tid] = lg[tid]; sB[tid] = lb[tid]; }
    __syncthreads();

    const int mh = w >> 2, nq = w & 3;
    const int mq = w & 3,  nh = w >> 2;

    float2 b1p[4], b2p[4];
    #pragma unroll
    for (int j = 0; j < 4; j++) {
        b1p[j] = *(const float2*)&sB1[nq * 32 + 8 * j + 2 * lr];
        b2p[j] = *(const float2*)&sB2[nh * 32 + 8 * j + 2 * lr];
    }

    const int numTiles = (NN + TILE - 1) / TILE;

    float pf[32];
    int t = blockIdx.x;
    if (t < numTiles) {
        const int n0g = t * TILE;
        #pragma unroll
        for (int v = 0; v < 32; v++) {
            int i = v * 256 + tid;
            int r = i >> 7, k = i & 127;
            int node = min(n0g + r, NN - 1);
            pf[v] = (k < HD) ? h[(size_t)node * HD + k]
                             : g_agg[(size_t)node * HD + (k - HD)];
        }
    }

    for (; t < numTiles; t += gridDim.x) {
        const int n0g = t * TILE;
        __syncthreads();

        #pragma unroll
        for (int v = 0; v < 32; v++) {
            int i = v * 256 + tid;
            int r = i >> 7, k = i & 127;
            sU[r * MHP + k] = f2tf(pf[v]);
        }
        __syncthreads();

        int tn = t + gridDim.x;
        if (tn < numTiles) {
            const int nn0 = tn * TILE;
            #pragma unroll
            for (int v = 0; v < 32; v++) {
                int i = v * 256 + tid;
                int r = i >> 7, k = i & 127;
                int node = min(nn0 + r, NN - 1);
                pf[v] = (k < HD) ? h[(size_t)node * HD + k]
                                 : g_agg[(size_t)node * HD + (k - HD)];
            }
        }

        float c1[2][4][4];
        #pragma unroll
        for (int i = 0; i < 2; i++)
            #pragma unroll
            for (int j = 0; j < 4; j++)
                #pragma unroll
                for (int q = 0; q < 4; q++) c1[i][j][q] = 0.f;

        for (int k = 0; k < MH; k += 8) {
            uint32_t a[2][4];
            #pragma unroll
            for (int i = 0; i < 2; i++) {
                int row = mh * 32 + 16 * i + lq;
                a[i][0] = __float_as_uint(sU[row * MHP + k + lr]);
                a[i][1] = __float_as_uint(sU[(row + 8) * MHP + k + lr]);
                a[i][2] = __float_as_uint(sU[row * MHP + k + 4 + lr]);
                a[i][3] = __float_as_uint(sU[(row + 8) * MHP + k + 4 + lr]);
            }
            #pragma unroll
            for (int j = 0; j < 4; j++) {
                int n0 = nq * 32 + 8 * j;
                int cs = (n0 + lq) ^ (lr << 3);
                uint32_t b0 = __float_as_uint(sW1[(k + lr) * MH + cs]);
                uint32_t b1 = __float_as_uint(sW1[(k + 4 + lr) * MH + cs]);
                mma_tf32(c1[0][j], a[0], b0, b1);
                mma_tf32(c1[1][j], a[1], b0, b1);
            }
        }

        #pragma unroll
        for (int i = 0; i < 2; i++) {
            #pragma unroll
            for (int j = 0; j < 4; j++) {
                int row = mh * 32 + 16 * i + lq;
                int col = nq * 32 + 8 * j + 2 * lr;
                uint2 v0, v1;
                v0.x = __float_as_uint(f2tf(fmaxf(c1[i][j][0] + b1p[j].x, 0.f)));
                v0.y = __float_as_uint(f2tf(fmaxf(c1[i][j][1] + b1p[j].y, 0.f)));
                v1.x = __float_as_uint(f2tf(fmaxf(c1[i][j][2] + b1p[j].x, 0.f)));
                v1.y = __float_as_uint(f2tf(fmaxf(c1[i][j][3] + b1p[j].y, 0.f)));
                *(uint2*)&sH[row * MHP + col]       = v0;
                *(uint2*)&sH[(row + 8) * MHP + col] = v1;
            }
        }
        __syncthreads();

        float c2[4][4];
        #pragma unroll
        for (int j = 0; j < 4; j++)
            #pragma unroll
            for (int q = 0; q < 4; q++) c2[j][q] = 0.f;

        const int m0 = mq * 16;
        for (int k = 0; k < MH; k += 8) {
            uint32_t a[4];
            int row = m0 + lq;
            a[0] = __float_as_uint(sH[row * MHP + k + lr]);
            a[1] = __float_as_uint(sH[(row + 8) * MHP + k + lr]);
            a[2] = __float_as_uint(sH[row * MHP + k + 4 + lr]);
            a[3] = __float_as_uint(sH[(row + 8) * MHP + k + 4 + lr]);
            #pragma unroll
            for (int j = 0; j < 4; j++) {
                int n0 = nh * 32 + 8 * j;
                int cs = (n0 + lq) ^ (lr << 3);
                uint32_t b0 = __float_as_uint(sW2[(k + lr) * HD + cs]);
                uint32_t b1 = __float_as_uint(sW2[(k + 4 + lr) * HD + cs]);
                mma_tf32(c2[j], a, b0, b1);
            }
        }

        {
            int r0 = m0 + lq;
            int r1 = r0 + 8;
            int g0 = n0g + r0, g1 = n0g + r1;
            #pragma unroll
            for (int j = 0; j < 4; j++) {
                int col = nh * 32 + 8 * j + 2 * lr;
                if (g0 < NN) {
                    float2 hv = *(const float2*)&h[(size_t)g0 * HD + col];
                    sO[r0 * 65 + col]     = c2[j][0] + b2p[j].x + hv.x;
                    sO[r0 * 65 + col + 1] = c2[j][1] + b2p[j].y + hv.y;
                }
                if (g1 < NN) {
                    float2 hv = *(const float2*)&h[(size_t)g1 * HD + col];
                    sO[r1 * 65 + col]     = c2[j][2] + b2p[j].x + hv.x;
                    sO[r1 * 65 + col + 1] = c2[j][3] + b2p[j].y + hv.y;
                }
            }
        }
        __syncthreads();

        if (tid < TILE) {
            float s = 0.f, s2 = 0.f;
            #pragma unroll 8
            for (int c = 0; c < HD; c++) {
                float v = sO[tid * 65 + c];
                s += v;
                s2 = fmaf(v, v, s2);
            }
            float mu  = s * (1.f / HD);
            float var = fmaxf(s2 * (1.f / HD) - mu * mu, 0.f);
            sMu[tid] = mu;
            sRs[tid] = rsqrtf(var + 1e-5f);
        }
        __syncthreads();

        for (int i = tid; i < TILE * HD; i += 256) {
            int r = i >> 6;
            int c = i & 63;
            int node = n0g + r;
            if (node < NN)
                out[(size_t)node * HD + c] =
                    (sO[r * 65 + c] - sMu[r]) * sRs[r] * sG[c] + sB[c];
        }
    }
}

// ---------------------------------------------------------------------------
extern "C" void kernel_launch(void* const* d_in, const int* in_sizes, int n_in,
                              void* d_out, int out_size)
{
    const float* h   = (const float*)d_in[0];
    const int*   ei  = (const int*)d_in[1];     // int32 (JAX default downcast)
    const float* ea  = (const float*)d_in[2];
    const float* eW1 = (const float*)d_in[3];
    const float* eb1 = (const float*)d_in[4];
    const float* eW2 = (const float*)d_in[5];
    const float* eb2 = (const float*)d_in[6];
    const float* nW1 = (const float*)d_in[7];
    const float* nb1 = (const float*)d_in[8];
    const float* nW2 = (const float*)d_in[9];
    const float* nb2 = (const float*)d_in[10];
    const float* lg  = (const float*)d_in[11];
    const float* lb  = (const float*)d_in[12];
    float*       out = (float*)d_out;

    const int smem_prep = (64 * 256 + 128 * 68) * 4;
    const int smem_edge = (8 * MH + MH * HD + ET * 12 + ET * MHP) * 4
                          + 2 * ET * 4;
    const int smem_node = (MH * MH + MH * HD + 2 * TILE * MHP + TILE * 65
                           + MH + 5 * HD + TILE) * 4;

    cudaFuncSetAttribute(prep_kernel, cudaFuncAttributeMaxDynamicSharedMemorySize, smem_prep);
    cudaFuncSetAttribute(edge_kernel, cudaFuncAttributeMaxDynamicSharedMemorySize, smem_edge);
    cudaFuncSetAttribute(node_kernel, cudaFuncAttributeMaxDynamicSharedMemorySize, smem_node);

    prep_kernel<<<148, 512, smem_prep>>>(h, eW1, eb1);
    edge_kernel<<<296, 256, smem_edge>>>(ei, ea, eW1, eW2, eb2);
    node_kernel<<<148, 256, smem_node>>>(h, nW1, nb1, nW2, nb2, lg, lb, out);
}

// round 10
// speedup vs baseline: 1.0739x; 1.0230x over previous
#include <cuda_runtime.h>
#include <cstdint>

#define NN    50000
#define NE    800000
#define HD    64
#define MH    128
#define MHP   132    // padded stride (mod 32 == 4 -> conflict-free A-frags)
#define ET    64     // edge tile

// scratch
__device__ float g_agg[(size_t)NN * HD];
__device__ float g_Pcat[(size_t)NN * 256];   // [ h@W_src | h@W_dst + eb1 ]

__device__ __forceinline__ float f2tf(float f) {
    uint32_t u;
    asm("cvt.rna.tf32.f32 %0, %1;" : "=r"(u) : "f"(f));
    return __uint_as_float(u);
}

__device__ __forceinline__ void mma_tf32(float c[4], const uint32_t a[4],
                                         uint32_t b0, uint32_t b1) {
    asm volatile(
        "mma.sync.aligned.m16n8k8.row.col.f32.tf32.tf32.f32 "
        "{%0,%1,%2,%3},{%4,%5,%6,%7},{%8,%9},{%0,%1,%2,%3};"
        : "+f"(c[0]), "+f"(c[1]), "+f"(c[2]), "+f"(c[3])
        : "r"(a[0]), "r"(a[1]), "r"(a[2]), "r"(a[3]), "r"(b0), "r"(b1));
}

// ---------------------------------------------------------------------------
// prep (persistent): Pcat[n,0:128] = h@W_src ; Pcat[n,128:256] = h@W_dst + eb1
// Also zeroes g_agg rows. 148 blocks x 512 threads, weights loaded ONCE.
// ---------------------------------------------------------------------------
__global__ __launch_bounds__(512, 1)
void prep_kernel(const float* __restrict__ h, const float* __restrict__ eW1,
                 const float* __restrict__ eb1)
{
    extern __shared__ float sm[];
    float* sW = sm;             // 64 x 256, col-swizzled
    float* sA = sW + 64 * 256;  // 128 x 68

    const int tid  = threadIdx.x;
    const int lane = tid & 31;
    const int w    = tid >> 5;
    const int lq   = lane >> 2;
    const int lr   = lane & 3;

    for (int i = tid; i < 64 * 256; i += 512) {
        int k = i >> 8, c = i & 255;
        float v = (c < MH) ? eW1[k * MH + c] : eW1[(64 + k) * MH + (c - MH)];
        sW[k * 256 + (c ^ ((k & 3) << 3))] = f2tf(v);
    }

    const int mh = w >> 2, nc = w & 3;   // 4 (m32) x 4 (n64)
    const int numTiles = (NN + 127) / 128;   // 391

    for (int tile = blockIdx.x; tile < numTiles; tile += gridDim.x) {
        const int n0g = tile * 128;
        __syncthreads();

        for (int i = tid; i < 128 * 16; i += 512) {
            int r = i >> 4, c4 = i & 15;
            int node = n0g + r;
            if (node < NN)
                reinterpret_cast<float4*>(g_agg)[(size_t)node * 16 + c4] =
                    make_float4(0.f, 0.f, 0.f, 0.f);
        }
        for (int i = tid; i < 128 * 64; i += 512) {
            int r = i >> 6, c = i & 63;
            int node = min(n0g + r, NN - 1);
            sA[r * 68 + c] = f2tf(h[(size_t)node * HD + c]);
        }
        __syncthreads();

        float acc[2][8][4];
        #pragma unroll
        for (int i = 0; i < 2; i++)
            #pragma unroll
            for (int j = 0; j < 8; j++)
                #pragma unroll
                for (int q = 0; q < 4; q++) acc[i][j][q] = 0.f;

        for (int k = 0; k < 64; k += 8) {
            uint32_t a[2][4];
            #pragma unroll
            for (int i = 0; i < 2; i++) {
                int row = mh * 32 + 16 * i + lq;
                a[i][0] = __float_as_uint(sA[row * 68 + k + lr]);
                a[i][1] = __float_as_uint(sA[(row + 8) * 68 + k + lr]);
                a[i][2] = __float_as_uint(sA[row * 68 + k + 4 + lr]);
                a[i][3] = __float_as_uint(sA[(row + 8) * 68 + k + 4 + lr]);
            }
            #pragma unroll
            for (int j = 0; j < 8; j++) {
                int n0 = nc * 64 + 8 * j;
                int cs = (n0 + lq) ^ (lr << 3);
                uint32_t b0 = __float_as_uint(sW[(k + lr) * 256 + cs]);
                uint32_t b1 = __float_as_uint(sW[(k + 4 + lr) * 256 + cs]);
                mma_tf32(acc[0][j], a[0], b0, b1);
                mma_tf32(acc[1][j], a[1], b0, b1);
            }
        }

        #pragma unroll
        for (int i = 0; i < 2; i++) {
            int r0 = mh * 32 + 16 * i + lq;
            int g0 = n0g + r0, g1 = g0 + 8;
            #pragma unroll
            for (int j = 0; j < 8; j++) {
                int col = nc * 64 + 8 * j + 2 * lr;
                float bx = 0.f, by = 0.f;
                if (col >= MH) {
                    bx = eb1[col - MH];
                    by = eb1[col - MH + 1];
                }
                if (g0 < NN)
                    *(float2*)&g_Pcat[(size_t)g0 * 256 + col] =
                        make_float2(acc[i][j][0] + bx, acc[i][j][1] + by);
                if (g1 < NN)
                    *(float2*)&g_Pcat[(size_t)g1 * 256 + col] =
                        make_float2(acc[i][j][2] + bx, acc[i][j][3] + by);
            }
        }
    }
}

// ---------------------------------------------------------------------------
// Edge kernel v4: NO SMEM staging of indices/ea (direct coalesced reg loads,
// prefetched one tile ahead), only sH remains shared; half-block named
// barriers decouple the two m-halves. 256 threads, 2 CTAs/SM.
// ---------------------------------------------------------------------------
__global__ __launch_bounds__(256, 2)
void edge_kernel(const int* __restrict__ ei,
                 const float* __restrict__ ea,
                 const float* __restrict__ eW1,
                 const float* __restrict__ eW2, const float* __restrict__ eb2)
{
    extern __shared__ float sm[];
    float* sWea = sm;                 // 8 x 128, col-swizzled
    float* sW2  = sWea + 8 * MH;      // 128 x 64, col-swizzled
    float* sH   = sW2 + MH * HD;      // 64 x 132

    const int tid  = threadIdx.x;
    const int lane = tid & 31;
    const int w    = tid >> 5;
    const int lq   = lane >> 2;
    const int lr   = lane & 3;
    const int mh   = w >> 2;   // 0..1 -> m32 half
    const int nq   = w & 3;    // 0..3 -> n32 (phase1) / n16 (phase2)
    const int barid = 1 + mh;  // named barrier per m-half (threads 0-127 / 128-255)

    for (int i = tid; i < 8 * MH; i += 256) {
        int k = i >> 7, c = i & 127;
        sWea[k * MH + (c ^ ((k & 3) << 3))] = f2tf(eW1[(2 * HD + k) * MH + c]);
    }
    for (int i = tid; i < MH * HD; i += 256) {
        int r = i >> 6, n = i & 63;
        sW2[r * HD + (n ^ ((r & 3) << 3))] = f2tf(eW2[i]);
    }
    __syncthreads();

    float2 b2p[2];
    #pragma unroll
    for (int j = 0; j < 2; j++) b2p[j] = *(const float2*)&eb2[nq * 16 + 8 * j + 2 * lr];

    // this thread's 4 edge rows within the tile: q = 2*i + m -> mh*32+16*i+8*m+lq
    int rofs[4];
    #pragma unroll
    for (int q = 0; q < 4; q++)
        rofs[q] = mh * 32 + 16 * (q >> 1) + 8 * (q & 1) + lq;

    const int numTiles = NE / ET;   // 12500
    const int G = gridDim.x;

    // prefetch first tile into registers
    int nS[4], nD[4];
    float nA[8];
    int t = blockIdx.x;
    if (t < numTiles) {
        const int e0 = t * ET;
        #pragma unroll
        for (int q = 0; q < 4; q++) {
            nS[q] = ei[e0 + rofs[q]];
            nD[q] = ei[NE + e0 + rofs[q]];
        }
        #pragma unroll
        for (int i = 0; i < 2; i++) {
            nA[4 * i + 0] = ea[(size_t)(e0 + rofs[2 * i])     * 8 + lr];
            nA[4 * i + 1] = ea[(size_t)(e0 + rofs[2 * i + 1]) * 8 + lr];
            nA[4 * i + 2] = ea[(size_t)(e0 + rofs[2 * i])     * 8 + 4 + lr];
            nA[4 * i + 3] = ea[(size_t)(e0 + rofs[2 * i + 1]) * 8 + 4 + lr];
        }
    }

    for (; t < numTiles; t += G) {
        // consume prefetched regs (clamp indices)
        int cS[4], cD[4];
        uint32_t af[2][4];
        #pragma unroll
        for (int q = 0; q < 4; q++) {
            cS[q] = min(max(nS[q], 0), NN - 1);
            cD[q] = min(max(nD[q], 0), NN - 1);
        }
        #pragma unroll
        for (int i = 0; i < 2; i++)
            #pragma unroll
            for (int q = 0; q < 4; q++)
                af[i][q] = __float_as_uint(f2tf(nA[4 * i + q]));

        // issue next tile's loads (hidden under this tile's compute)
        int tn = t + G;
        if (tn < numTiles) {
            const int en = tn * ET;
            #pragma unroll
            for (int q = 0; q < 4; q++) {
                nS[q] = ei[en + rofs[q]];
                nD[q] = ei[NE + en + rofs[q]];
            }
            #pragma unroll
            for (int i = 0; i < 2; i++) {
                nA[4 * i + 0] = ea[(size_t)(en + rofs[2 * i])     * 8 + lr];
                nA[4 * i + 1] = ea[(size_t)(en + rofs[2 * i + 1]) * 8 + lr];
                nA[4 * i + 2] = ea[(size_t)(en + rofs[2 * i])     * 8 + 4 + lr];
                nA[4 * i + 3] = ea[(size_t)(en + rofs[2 * i + 1]) * 8 + 4 + lr];
            }
        }

        // ---- phase 1: [64,8] @ [8,128] from registers ----
        float c1[2][4][4];
        #pragma unroll
        for (int i = 0; i < 2; i++)
            #pragma unroll
            for (int j = 0; j < 4; j++)
                #pragma unroll
                for (int q = 0; q < 4; q++) c1[i][j][q] = 0.f;

        #pragma unroll
        for (int j = 0; j < 4; j++) {
            int n0 = nq * 32 + 8 * j;
            int cs = (n0 + lq) ^ (lr << 3);
            uint32_t b0 = __float_as_uint(sWea[lr * MH + cs]);
            uint32_t b1 = __float_as_uint(sWea[(4 + lr) * MH + cs]);
            mma_tf32(c1[0][j], af[0], b0, b1);
            mma_tf32(c1[1][j], af[1], b0, b1);
        }

        // gathered Pcat (bias pre-folded), relu -> sH
        #pragma unroll
        for (int i = 0; i < 2; i++) {
            int r0 = rofs[2 * i];
            int r1 = rofs[2 * i + 1];
            const float* ps0 = g_Pcat + (size_t)cS[2 * i] * 256;
            const float* pd0 = g_Pcat + (size_t)cD[2 * i] * 256 + MH;
            const float* ps1 = g_Pcat + (size_t)cS[2 * i + 1] * 256;
            const float* pd1 = g_Pcat + (size_t)cD[2 * i + 1] * 256 + MH;
            #pragma unroll
            for (int j = 0; j < 4; j++) {
                int col = nq * 32 + 8 * j + 2 * lr;
                float2 s0 = *(const float2*)&ps0[col];
                float2 d0 = *(const float2*)&pd0[col];
                float2 s1 = *(const float2*)&ps1[col];
                float2 d1 = *(const float2*)&pd1[col];
                uint2 v0, v1;
                v0.x = __float_as_uint(f2tf(fmaxf(c1[i][j][0] + s0.x + d0.x, 0.f)));
                v0.y = __float_as_uint(f2tf(fmaxf(c1[i][j][1] + s0.y + d0.y, 0.f)));
                v1.x = __float_as_uint(f2tf(fmaxf(c1[i][j][2] + s1.x + d1.x, 0.f)));
                v1.y = __float_as_uint(f2tf(fmaxf(c1[i][j][3] + s1.y + d1.y, 0.f)));
                *(uint2*)&sH[r0 * MHP + col] = v0;
                *(uint2*)&sH[r1 * MHP + col] = v1;
            }
        }

        // half-block barrier: my m-half's sH writes visible to its 4 warps
        asm volatile("bar.sync %0, 128;" :: "r"(barid) : "memory");

        // ---- phase 2: [32,128] @ [128,64] (own m-half rows only) ----
        float c2[2][2][4];
        #pragma unroll
        for (int i = 0; i < 2; i++)
            #pragma unroll
            for (int j = 0; j < 2; j++)
                #pragma unroll
                for (int q = 0; q < 4; q++) c2[i][j][q] = 0.f;

        for (int k = 0; k < MH; k += 8) {
            uint32_t a[2][4];
            #pragma unroll
            for (int i = 0; i < 2; i++) {
                int row = rofs[2 * i];
                a[i][0] = __float_as_uint(sH[row * MHP + k + lr]);
                a[i][1] = __float_as_uint(sH[(row + 8) * MHP + k + lr]);
                a[i][2] = __float_as_uint(sH[row * MHP + k + 4 + lr]);
                a[i][3] = __float_as_uint(sH[(row + 8) * MHP + k + 4 + lr]);
            }
            #pragma unroll
            for (int j = 0; j < 2; j++) {
                int n0 = nq * 16 + 8 * j;
                int cs = (n0 + lq) ^ (lr << 3);
                uint32_t b0 = __float_as_uint(sW2[(k + lr) * HD + cs]);
                uint32_t b1 = __float_as_uint(sW2[(k + 4 + lr) * HD + cs]);
                mma_tf32(c2[0][j], a[0], b0, b1);
                mma_tf32(c2[1][j], a[1], b0, b1);
            }
        }

        // half-block barrier: sH reads done before next tile overwrites
        asm volatile("bar.sync %0, 128;" :: "r"(barid) : "memory");

        // scatter-add (after barrier so atomic issue overlaps next tile)
        #pragma unroll
        for (int i = 0; i < 2; i++) {
            int d0 = cD[2 * i], d1 = cD[2 * i + 1];
            #pragma unroll
            for (int j = 0; j < 2; j++) {
                float u0 = c2[i][j][0] + b2p[j].x;
                float u1 = c2[i][j][1] + b2p[j].y;
                float u2 = c2[i][j][2] + b2p[j].x;
                float u3 = c2[i][j][3] + b2p[j].y;
                float w0 = __shfl_xor_sync(0xffffffffu, u0, 1);
                float w1 = __shfl_xor_sync(0xffffffffu, u1, 1);
                float w2 = __shfl_xor_sync(0xffffffffu, u2, 1);
                float w3 = __shfl_xor_sync(0xffffffffu, u3, 1);
                if (!(lr & 1)) {
                    int col = nq * 16 + 8 * j + (lr & 2) * 2;
                    float* p0 = g_agg + (size_t)d0 * HD + col;
                    float* p1 = g_agg + (size_t)d1 * HD + col;
                    asm volatile("red.global.add.v4.f32 [%0], {%1, %2, %3, %4};"
                                 :: "l"(p0), "f"(u0), "f"(u1), "f"(w0), "f"(w1)
                                 : "memory");
                    asm volatile("red.global.add.v4.f32 [%0], {%1, %2, %3, %4};"
                                 :: "l"(p1), "f"(u2), "f"(u3), "f"(w2), "f"(w3)
                                 : "memory");
                }
            }
        }
    }
}

// ---------------------------------------------------------------------------
// Node kernel: tf32 MMA, 64 nodes/tile, 256 threads, next-tile reg prefetch.
// ---------------------------------------------------------------------------
#define TILE 64
__global__ __launch_bounds__(256, 1)
void node_kernel(const float* __restrict__ h,
                 const float* __restrict__ nW1, const float* __restrict__ nb1,
                 const float* __restrict__ nW2, const float* __restrict__ nb2,
                 const float* __restrict__ lg,  const float* __restrict__ lb,
                 float* __restrict__ out)
{
    extern __shared__ float sm[];
    float* sW1 = sm;
    float* sW2 = sW1 + MH * MH;
    float* sU  = sW2 + MH * HD;
    float* sH  = sU  + TILE * MHP;
    float* sO  = sH  + TILE * MHP;
    float* sB1 = sO  + TILE * 65;
    float* sB2 = sB1 + MH;
    float* sG  = sB2 + HD;
    float* sB  = sG  + HD;
    float* sMu = sB  + HD;
    float* sRs = sMu + TILE;

    const int tid  = threadIdx.x;
    const int lane = tid & 31;
    const int w    = tid >> 5;
    const int lq   = lane >> 2;
    const int lr   = lane & 3;

    for (int i = tid; i < MH * MH; i += 256) {
        int r = i >> 7, n = i & 127;
        sW1[r * MH + (n ^ ((r & 3) << 3))] = f2tf(nW1[i]);
    }
    for (int i = tid; i < MH * HD; i += 256) {
        int r = i >> 6, n = i & 63;
        sW2[r * HD + (n ^ ((r & 3) << 3))] = f2tf(nW2[i]);
    }
    for (int i = tid; i < MH; i += 256) sB1[i] = nb1[i];
    if (tid < HD) { sB2[tid] = nb2[tid]; sG[tid] = lg[tid]; sB[tid] = lb[tid]; }
    __syncthreads();

    const int mh = w >> 2, nq = w & 3;
    const int mq = w & 3,  nh = w >> 2;

    float2 b1p[4], b2p[4];
    #pragma unroll
    for (int j = 0; j < 4; j++) {
        b1p[j] = *(const float2*)&sB1[nq * 32 + 8 * j + 2 * lr];
        b2p[j] = *(const float2*)&sB2[nh * 32 + 8 * j + 2 * lr];
    }

    const int numTiles = (NN + TILE - 1) / TILE;

    float pf[32];
    int t = blockIdx.x;
    if (t < numTiles) {
        const int n0g = t * TILE;
        #pragma unroll
        for (int v = 0; v < 32; v++) {
            int i = v * 256 + tid;
            int r = i >> 7, k = i & 127;
            int node = min(n0g + r, NN - 1);
            pf[v] = (k < HD) ? h[(size_t)node * HD + k]
                             : g_agg[(size_t)node * HD + (k - HD)];
        }
    }

    for (; t < numTiles; t += gridDim.x) {
        const int n0g = t * TILE;
        __syncthreads();

        #pragma unroll
        for (int v = 0; v < 32; v++) {
            int i = v * 256 + tid;
            int r = i >> 7, k = i & 127;
            sU[r * MHP + k] = f2tf(pf[v]);
        }
        __syncthreads();

        int tn = t + gridDim.x;
        if (tn < numTiles) {
            const int nn0 = tn * TILE;
            #pragma unroll
            for (int v = 0; v < 32; v++) {
                int i = v * 256 + tid;
                int r = i >> 7, k = i & 127;
                int node = min(nn0 + r, NN - 1);
                pf[v] = (k < HD) ? h[(size_t)node * HD + k]
                                 : g_agg[(size_t)node * HD + (k - HD)];
            }
        }

        float c1[2][4][4];
        #pragma unroll
        for (int i = 0; i < 2; i++)
            #pragma unroll
            for (int j = 0; j < 4; j++)
                #pragma unroll
                for (int q = 0; q < 4; q++) c1[i][j][q] = 0.f;

        for (int k = 0; k < MH; k += 8) {
            uint32_t a[2][4];
            #pragma unroll
            for (int i = 0; i < 2; i++) {
                int row = mh * 32 + 16 * i + lq;
                a[i][0] = __float_as_uint(sU[row * MHP + k + lr]);
                a[i][1] = __float_as_uint(sU[(row + 8) * MHP + k + lr]);
                a[i][2] = __float_as_uint(sU[row * MHP + k + 4 + lr]);
                a[i][3] = __float_as_uint(sU[(row + 8) * MHP + k + 4 + lr]);
            }
            #pragma unroll
            for (int j = 0; j < 4; j++) {
                int n0 = nq * 32 + 8 * j;
                int cs = (n0 + lq) ^ (lr << 3);
                uint32_t b0 = __float_as_uint(sW1[(k + lr) * MH + cs]);
                uint32_t b1 = __float_as_uint(sW1[(k + 4 + lr) * MH + cs]);
                mma_tf32(c1[0][j], a[0], b0, b1);
                mma_tf32(c1[1][j], a[1], b0, b1);
            }
        }

        #pragma unroll
        for (int i = 0; i < 2; i++) {
            #pragma unroll
            for (int j = 0; j < 4; j++) {
                int row = mh * 32 + 16 * i + lq;
                int col = nq * 32 + 8 * j + 2 * lr;
                uint2 v0, v1;
                v0.x = __float_as_uint(f2tf(fmaxf(c1[i][j][0] + b1p[j].x, 0.f)));
                v0.y = __float_as_uint(f2tf(fmaxf(c1[i][j][1] + b1p[j].y, 0.f)));
                v1.x = __float_as_uint(f2tf(fmaxf(c1[i][j][2] + b1p[j].x, 0.f)));
                v1.y = __float_as_uint(f2tf(fmaxf(c1[i][j][3] + b1p[j].y, 0.f)));
                *(uint2*)&sH[row * MHP + col]       = v0;
                *(uint2*)&sH[(row + 8) * MHP + col] = v1;
            }
        }
        __syncthreads();

        float c2[4][4];
        #pragma unroll
        for (int j = 0; j < 4; j++)
            #pragma unroll
            for (int q = 0; q < 4; q++) c2[j][q] = 0.f;

        const int m0 = mq * 16;
        for (int k = 0; k < MH; k += 8) {
            uint32_t a[4];
            int row = m0 + lq;
            a[0] = __float_as_uint(sH[row * MHP + k + lr]);
            a[1] = __float_as_uint(sH[(row + 8) * MHP + k + lr]);
            a[2] = __float_as_uint(sH[row * MHP + k + 4 + lr]);
            a[3] = __float_as_uint(sH[(row + 8) * MHP + k + 4 + lr]);
            #pragma unroll
            for (int j = 0; j < 4; j++) {
                int n0 = nh * 32 + 8 * j;
                int cs = (n0 + lq) ^ (lr << 3);
                uint32_t b0 = __float_as_uint(sW2[(k + lr) * HD + cs]);
                uint32_t b1 = __float_as_uint(sW2[(k + 4 + lr) * HD + cs]);
                mma_tf32(c2[j], a, b0, b1);
            }
        }

        {
            int r0 = m0 + lq;
            int r1 = r0 + 8;
            int g0 = n0g + r0, g1 = n0g + r1;
            #pragma unroll
            for (int j = 0; j < 4; j++) {
                int col = nh * 32 + 8 * j + 2 * lr;
                if (g0 < NN) {
                    float2 hv = *(const float2*)&h[(size_t)g0 * HD + col];
                    sO[r0 * 65 + col]     = c2[j][0] + b2p[j].x + hv.x;
                    sO[r0 * 65 + col + 1] = c2[j][1] + b2p[j].y + hv.y;
                }
                if (g1 < NN) {
                    float2 hv = *(const float2*)&h[(size_t)g1 * HD + col];
                    sO[r1 * 65 + col]     = c2[j][2] + b2p[j].x + hv.x;
                    sO[r1 * 65 + col + 1] = c2[j][3] + b2p[j].y + hv.y;
                }
            }
        }
        __syncthreads();

        if (tid < TILE) {
            float s = 0.f, s2 = 0.f;
            #pragma unroll 8
            for (int c = 0; c < HD; c++) {
                float v = sO[tid * 65 + c];
                s += v;
                s2 = fmaf(v, v, s2);
            }
            float mu  = s * (1.f / HD);
            float var = fmaxf(s2 * (1.f / HD) - mu * mu, 0.f);
            sMu[tid] = mu;
            sRs[tid] = rsqrtf(var + 1e-5f);
        }
        __syncthreads();

        for (int i = tid; i < TILE * HD; i += 256) {
            int r = i >> 6;
            int c = i & 63;
            int node = n0g + r;
            if (node < NN)
                out[(size_t)node * HD + c] =
                    (sO[r * 65 + c] - sMu[r]) * sRs[r] * sG[c] + sB[c];
        }
    }
}

// ---------------------------------------------------------------------------
extern "C" void kernel_launch(void* const* d_in, const int* in_sizes, int n_in,
                              void* d_out, int out_size)
{
    const float* h   = (const float*)d_in[0];
    const int*   ei  = (const int*)d_in[1];     // int32 (JAX default downcast)
    const float* ea  = (const float*)d_in[2];
    const float* eW1 = (const float*)d_in[3];
    const float* eb1 = (const float*)d_in[4];
    const float* eW2 = (const float*)d_in[5];
    const float* eb2 = (const float*)d_in[6];
    const float* nW1 = (const float*)d_in[7];
    const float* nb1 = (const float*)d_in[8];
    const float* nW2 = (const float*)d_in[9];
    const float* nb2 = (const float*)d_in[10];
    const float* lg  = (const float*)d_in[11];
    const float* lb  = (const float*)d_in[12];
    float*       out = (float*)d_out;

    const int smem_prep = (64 * 256 + 128 * 68) * 4;
    const int smem_edge = (8 * MH + MH * HD + ET * MHP) * 4;
    const int smem_node = (MH * MH + MH * HD + 2 * TILE * MHP + TILE * 65
                           + MH + 5 * HD + TILE) * 4;

    cudaFuncSetAttribute(prep_kernel, cudaFuncAttributeMaxDynamicSharedMemorySize, smem_prep);
    cudaFuncSetAttribute(edge_kernel, cudaFuncAttributeMaxDynamicSharedMemorySize, smem_edge);
    cudaFuncSetAttribute(node_kernel, cudaFuncAttributeMaxDynamicSharedMemorySize, smem_node);

    prep_kernel<<<148, 512, smem_prep>>>(h, eW1, eb1);
    edge_kernel<<<296, 256, smem_edge>>>(ei, ea, eW1, eW2, eb2);
    node_kernel<<<148, 256, smem_node>>>(h, nW1, nb1, nW2, nb2, lg, lb, out);
}

// round 11
// speedup vs baseline: 1.1216x; 1.0445x over previous
#include <cuda_runtime.h>
#include <cstdint>

#define NN    50000
#define NE    800000
#define HD    64
#define MH    128
#define MHP   132    // padded stride (mod 32 == 4 -> conflict-free A-frags)
#define ET    64     // edge tile

// scratch
__device__ float g_agg[(size_t)NN * HD];
__device__ float g_Pcat[(size_t)NN * 256];   // [ h@W_src | h@W_dst + eb1 ]

__device__ __forceinline__ float f2tf(float f) {
    uint32_t u;
    asm("cvt.rna.tf32.f32 %0, %1;" : "=r"(u) : "f"(f));
    return __uint_as_float(u);
}

__device__ __forceinline__ void mma_tf32(float c[4], const uint32_t a[4],
                                         uint32_t b0, uint32_t b1) {
    asm volatile(
        "mma.sync.aligned.m16n8k8.row.col.f32.tf32.tf32.f32 "
        "{%0,%1,%2,%3},{%4,%5,%6,%7},{%8,%9},{%0,%1,%2,%3};"
        : "+f"(c[0]), "+f"(c[1]), "+f"(c[2]), "+f"(c[3])
        : "r"(a[0]), "r"(a[1]), "r"(a[2]), "r"(a[3]), "r"(b0), "r"(b1));
}

// ---------------------------------------------------------------------------
// prep (persistent): Pcat[n,0:128] = h@W_src ; Pcat[n,128:256] = h@W_dst + eb1
// Also zeroes g_agg rows. 148 blocks x 512 threads, weights loaded ONCE.
// ---------------------------------------------------------------------------
__global__ __launch_bounds__(512, 1)
void prep_kernel(const float* __restrict__ h, const float* __restrict__ eW1,
                 const float* __restrict__ eb1)
{
    extern __shared__ float sm[];
    float* sW = sm;             // 64 x 256, col-swizzled
    float* sA = sW + 64 * 256;  // 128 x 68

    const int tid  = threadIdx.x;
    const int lane = tid & 31;
    const int w    = tid >> 5;
    const int lq   = lane >> 2;
    const int lr   = lane & 3;

    for (int i = tid; i < 64 * 256; i += 512) {
        int k = i >> 8, c = i & 255;
        float v = (c < MH) ? eW1[k * MH + c] : eW1[(64 + k) * MH + (c - MH)];
        sW[k * 256 + (c ^ ((k & 3) << 3))] = f2tf(v);
    }

    const int mh = w >> 2, nc = w & 3;   // 4 (m32) x 4 (n64)
    const int numTiles = (NN + 127) / 128;   // 391

    for (int tile = blockIdx.x; tile < numTiles; tile += gridDim.x) {
        const int n0g = tile * 128;
        __syncthreads();

        for (int i = tid; i < 128 * 16; i += 512) {
            int r = i >> 4, c4 = i & 15;
            int node = n0g + r;
            if (node < NN)
                reinterpret_cast<float4*>(g_agg)[(size_t)node * 16 + c4] =
                    make_float4(0.f, 0.f, 0.f, 0.f);
        }
        for (int i = tid; i < 128 * 64; i += 512) {
            int r = i >> 6, c = i & 63;
            int node = min(n0g + r, NN - 1);
            sA[r * 68 + c] = f2tf(h[(size_t)node * HD + c]);
        }
        __syncthreads();

        float acc[2][8][4];
        #pragma unroll
        for (int i = 0; i < 2; i++)
            #pragma unroll
            for (int j = 0; j < 8; j++)
                #pragma unroll
                for (int q = 0; q < 4; q++) acc[i][j][q] = 0.f;

        for (int k = 0; k < 64; k += 8) {
            uint32_t a[2][4];
            #pragma unroll
            for (int i = 0; i < 2; i++) {
                int row = mh * 32 + 16 * i + lq;
                a[i][0] = __float_as_uint(sA[row * 68 + k + lr]);
                a[i][1] = __float_as_uint(sA[(row + 8) * 68 + k + lr]);
                a[i][2] = __float_as_uint(sA[row * 68 + k + 4 + lr]);
                a[i][3] = __float_as_uint(sA[(row + 8) * 68 + k + 4 + lr]);
            }
            #pragma unroll
            for (int j = 0; j < 8; j++) {
                int n0 = nc * 64 + 8 * j;
                int cs = (n0 + lq) ^ (lr << 3);
                uint32_t b0 = __float_as_uint(sW[(k + lr) * 256 + cs]);
                uint32_t b1 = __float_as_uint(sW[(k + 4 + lr) * 256 + cs]);
                mma_tf32(acc[0][j], a[0], b0, b1);
                mma_tf32(acc[1][j], a[1], b0, b1);
            }
        }

        #pragma unroll
        for (int i = 0; i < 2; i++) {
            int r0 = mh * 32 + 16 * i + lq;
            int g0 = n0g + r0, g1 = g0 + 8;
            #pragma unroll
            for (int j = 0; j < 8; j++) {
                int col = nc * 64 + 8 * j + 2 * lr;
                float bx = 0.f, by = 0.f;
                if (col >= MH) {
                    bx = eb1[col - MH];
                    by = eb1[col - MH + 1];
                }
                if (g0 < NN)
                    *(float2*)&g_Pcat[(size_t)g0 * 256 + col] =
                        make_float2(acc[i][j][0] + bx, acc[i][j][1] + by);
                if (g1 < NN)
                    *(float2*)&g_Pcat[(size_t)g1 * 256 + col] =
                        make_float2(acc[i][j][2] + bx, acc[i][j][3] + by);
            }
        }
    }
}

// ---------------------------------------------------------------------------
// Edge kernel v5: direct reg loads + half-block barriers (R10), phase-2 now
// m32 x n32 warp tiles — only warps nq<2 of each m-half compute phase 2 and
// scatter; SMEM crossbar traffic drops 192KB -> 128KB per tile per CTA.
// ---------------------------------------------------------------------------
__global__ __launch_bounds__(256, 2)
void edge_kernel(const int* __restrict__ ei,
                 const float* __restrict__ ea,
                 const float* __restrict__ eW1,
                 const float* __restrict__ eW2, const float* __restrict__ eb2)
{
    extern __shared__ float sm[];
    float* sWea = sm;                 // 8 x 128, col-swizzled
    float* sW2  = sWea + 8 * MH;      // 128 x 64, col-swizzled
    float* sH   = sW2 + MH * HD;      // 64 x 132

    const int tid  = threadIdx.x;
    const int lane = tid & 31;
    const int w    = tid >> 5;
    const int lq   = lane >> 2;
    const int lr   = lane & 3;
    const int mh   = w >> 2;   // 0..1 -> m32 half
    const int nq   = w & 3;    // 0..3 -> n32 (phase1); phase2 active iff nq<2
    const int barid = 1 + mh;

    for (int i = tid; i < 8 * MH; i += 256) {
        int k = i >> 7, c = i & 127;
        sWea[k * MH + (c ^ ((k & 3) << 3))] = f2tf(eW1[(2 * HD + k) * MH + c]);
    }
    for (int i = tid; i < MH * HD; i += 256) {
        int r = i >> 6, n = i & 63;
        sW2[r * HD + (n ^ ((r & 3) << 3))] = f2tf(eW2[i]);
    }
    __syncthreads();

    // phase-2 bias fragments (n32 tile): safe index via (nq&1)
    float2 b2p[4];
    #pragma unroll
    for (int j = 0; j < 4; j++)
        b2p[j] = *(const float2*)&eb2[(nq & 1) * 32 + 8 * j + 2 * lr];

    int rofs[4];
    #pragma unroll
    for (int q = 0; q < 4; q++)
        rofs[q] = mh * 32 + 16 * (q >> 1) + 8 * (q & 1) + lq;

    const int numTiles = NE / ET;   // 12500
    const int G = gridDim.x;

    // prefetch first tile into registers
    int nS[4], nD[4];
    float nA[8];
    int t = blockIdx.x;
    if (t < numTiles) {
        const int e0 = t * ET;
        #pragma unroll
        for (int q = 0; q < 4; q++) {
            nS[q] = ei[e0 + rofs[q]];
            nD[q] = ei[NE + e0 + rofs[q]];
        }
        #pragma unroll
        for (int i = 0; i < 2; i++) {
            nA[4 * i + 0] = ea[(size_t)(e0 + rofs[2 * i])     * 8 + lr];
            nA[4 * i + 1] = ea[(size_t)(e0 + rofs[2 * i + 1]) * 8 + lr];
            nA[4 * i + 2] = ea[(size_t)(e0 + rofs[2 * i])     * 8 + 4 + lr];
            nA[4 * i + 3] = ea[(size_t)(e0 + rofs[2 * i + 1]) * 8 + 4 + lr];
        }
    }

    for (; t < numTiles; t += G) {
        int cS[4], cD[4];
        uint32_t af[2][4];
        #pragma unroll
        for (int q = 0; q < 4; q++) {
            cS[q] = min(max(nS[q], 0), NN - 1);
            cD[q] = min(max(nD[q], 0), NN - 1);
        }
        #pragma unroll
        for (int i = 0; i < 2; i++)
            #pragma unroll
            for (int q = 0; q < 4; q++)
                af[i][q] = __float_as_uint(f2tf(nA[4 * i + q]));

        int tn = t + G;
        if (tn < numTiles) {
            const int en = tn * ET;
            #pragma unroll
            for (int q = 0; q < 4; q++) {
                nS[q] = ei[en + rofs[q]];
                nD[q] = ei[NE + en + rofs[q]];
            }
            #pragma unroll
            for (int i = 0; i < 2; i++) {
                nA[4 * i + 0] = ea[(size_t)(en + rofs[2 * i])     * 8 + lr];
                nA[4 * i + 1] = ea[(size_t)(en + rofs[2 * i + 1]) * 8 + lr];
                nA[4 * i + 2] = ea[(size_t)(en + rofs[2 * i])     * 8 + 4 + lr];
                nA[4 * i + 3] = ea[(size_t)(en + rofs[2 * i + 1]) * 8 + 4 + lr];
            }
        }

        // ---- phase 1: [64,8] @ [8,128] from registers (all 8 warps) ----
        float c1[2][4][4];
        #pragma unroll
        for (int i = 0; i < 2; i++)
            #pragma unroll
            for (int j = 0; j < 4; j++)
                #pragma unroll
                for (int q = 0; q < 4; q++) c1[i][j][q] = 0.f;

        #pragma unroll
        for (int j = 0; j < 4; j++) {
            int n0 = nq * 32 + 8 * j;
            int cs = (n0 + lq) ^ (lr << 3);
            uint32_t b0 = __float_as_uint(sWea[lr * MH + cs]);
            uint32_t b1 = __float_as_uint(sWea[(4 + lr) * MH + cs]);
            mma_tf32(c1[0][j], af[0], b0, b1);
            mma_tf32(c1[1][j], af[1], b0, b1);
        }

        // gathered Pcat (bias pre-folded), relu -> sH
        #pragma unroll
        for (int i = 0; i < 2; i++) {
            int r0 = rofs[2 * i];
            int r1 = rofs[2 * i + 1];
            const float* ps0 = g_Pcat + (size_t)cS[2 * i] * 256;
            const float* pd0 = g_Pcat + (size_t)cD[2 * i] * 256 + MH;
            const float* ps1 = g_Pcat + (size_t)cS[2 * i + 1] * 256;
            const float* pd1 = g_Pcat + (size_t)cD[2 * i + 1] * 256 + MH;
            #pragma unroll
            for (int j = 0; j < 4; j++) {
                int col = nq * 32 + 8 * j + 2 * lr;
                float2 s0 = *(const float2*)&ps0[col];
                float2 d0 = *(const float2*)&pd0[col];
                float2 s1 = *(const float2*)&ps1[col];
                float2 d1 = *(const float2*)&pd1[col];
                uint2 v0, v1;
                v0.x = __float_as_uint(f2tf(fmaxf(c1[i][j][0] + s0.x + d0.x, 0.f)));
                v0.y = __float_as_uint(f2tf(fmaxf(c1[i][j][1] + s0.y + d0.y, 0.f)));
                v1.x = __float_as_uint(f2tf(fmaxf(c1[i][j][2] + s1.x + d1.x, 0.f)));
                v1.y = __float_as_uint(f2tf(fmaxf(c1[i][j][3] + s1.y + d1.y, 0.f)));
                *(uint2*)&sH[r0 * MHP + col] = v0;
                *(uint2*)&sH[r1 * MHP + col] = v1;
            }
        }

        // half-block barrier: this m-half's sH writes visible to its warps
        asm volatile("bar.sync %0, 128;" :: "r"(barid) : "memory");

        // ---- phase 2: [32,128] @ [128,32] per active warp (nq < 2) ----
        float c2[2][4][4];
        if (nq < 2) {
            #pragma unroll
            for (int i = 0; i < 2; i++)
                #pragma unroll
                for (int j = 0; j < 4; j++)
                    #pragma unroll
                    for (int q = 0; q < 4; q++) c2[i][j][q] = 0.f;

            for (int k = 0; k < MH; k += 8) {
                uint32_t a[2][4];
                #pragma unroll
                for (int i = 0; i < 2; i++) {
                    int row = rofs[2 * i];
                    a[i][0] = __float_as_uint(sH[row * MHP + k + lr]);
                    a[i][1] = __float_as_uint(sH[(row + 8) * MHP + k + lr]);
                    a[i][2] = __float_as_uint(sH[row * MHP + k + 4 + lr]);
                    a[i][3] = __float_as_uint(sH[(row + 8) * MHP + k + 4 + lr]);
                }
                #pragma unroll
                for (int j = 0; j < 4; j++) {
                    int n0 = nq * 32 + 8 * j;
                    int cs = (n0 + lq) ^ (lr << 3);
                    uint32_t b0 = __float_as_uint(sW2[(k + lr) * HD + cs]);
                    uint32_t b1 = __float_as_uint(sW2[(k + 4 + lr) * HD + cs]);
                    mma_tf32(c2[0][j], a[0], b0, b1);
                    mma_tf32(c2[1][j], a[1], b0, b1);
                }
            }
        }

        // half-block barrier: sH reads done before next tile overwrites
        asm volatile("bar.sync %0, 128;" :: "r"(barid) : "memory");

        // scatter-add (active warps only; after barrier -> overlaps next tile)
        if (nq < 2) {
            #pragma unroll
            for (int i = 0; i < 2; i++) {
                int d0 = cD[2 * i], d1 = cD[2 * i + 1];
                #pragma unroll
                for (int j = 0; j < 4; j++) {
                    float u0 = c2[i][j][0] + b2p[j].x;
                    float u1 = c2[i][j][1] + b2p[j].y;
                    float u2 = c2[i][j][2] + b2p[j].x;
                    float u3 = c2[i][j][3] + b2p[j].y;
                    float w0 = __shfl_xor_sync(0xffffffffu, u0, 1);
                    float w1 = __shfl_xor_sync(0xffffffffu, u1, 1);
                    float w2 = __shfl_xor_sync(0xffffffffu, u2, 1);
                    float w3 = __shfl_xor_sync(0xffffffffu, u3, 1);
                    if (!(lr & 1)) {
                        int col = nq * 32 + 8 * j + (lr & 2) * 2;
                        float* p0 = g_agg + (size_t)d0 * HD + col;
                        float* p1 = g_agg + (size_t)d1 * HD + col;
                        asm volatile("red.global.add.v4.f32 [%0], {%1, %2, %3, %4};"
                                     :: "l"(p0), "f"(u0), "f"(u1), "f"(w0), "f"(w1)
                                     : "memory");
                        asm volatile("red.global.add.v4.f32 [%0], {%1, %2, %3, %4};"
                                     :: "l"(p1), "f"(u2), "f"(u3), "f"(w2), "f"(w3)
                                     : "memory");
                    }
                }
            }
        }
    }
}

// ---------------------------------------------------------------------------
// Node kernel: tf32 MMA, 64 nodes/tile, 256 threads, next-tile reg prefetch.
// ---------------------------------------------------------------------------
#define TILE 64
__global__ __launch_bounds__(256, 1)
void node_kernel(const float* __restrict__ h,
                 const float* __restrict__ nW1, const float* __restrict__ nb1,
                 const float* __restrict__ nW2, const float* __restrict__ nb2,
                 const float* __restrict__ lg,  const float* __restrict__ lb,
                 float* __restrict__ out)
{
    extern __shared__ float sm[];
    float* sW1 = sm;
    float* sW2 = sW1 + MH * MH;
    float* sU  = sW2 + MH * HD;
    float* sH  = sU  + TILE * MHP;
    float* sO  = sH  + TILE * MHP;
    float* sB1 = sO  + TILE * 65;
    float* sB2 = sB1 + MH;
    float* sG  = sB2 + HD;
    float* sB  = sG  + HD;
    float* sMu = sB  + HD;
    float* sRs = sMu + TILE;

    const int tid  = threadIdx.x;
    const int lane = tid & 31;
    const int w    = tid >> 5;
    const int lq   = lane >> 2;
    const int lr   = lane & 3;

    for (int i = tid; i < MH * MH; i += 256) {
        int r = i >> 7, n = i & 127;
        sW1[r * MH + (n ^ ((r & 3) << 3))] = f2tf(nW1[i]);
    }
    for (int i = tid; i < MH * HD; i += 256) {
        int r = i >> 6, n = i & 63;
        sW2[r * HD + (n ^ ((r & 3) << 3))] = f2tf(nW2[i]);
    }
    for (int i = tid; i < MH; i += 256) sB1[i] = nb1[i];
    if (tid < HD) { sB2[tid] = nb2[tid]; sG[tid] = lg[tid]; sB[tid] = lb[tid]; }
    __syncthreads();

    const int mh = w >> 2, nq = w & 3;
    const int mq = w & 3,  nh = w >> 2;

    float2 b1p[4], b2p[4];
    #pragma unroll
    for (int j = 0; j < 4; j++) {
        b1p[j] = *(const float2*)&sB1[nq * 32 + 8 * j + 2 * lr];
        b2p[j] = *(const float2*)&sB2[nh * 32 + 8 * j + 2 * lr];
    }

    const int numTiles = (NN + TILE - 1) / TILE;

    float pf[32];
    int t = blockIdx.x;
    if (t < numTiles) {
        const int n0g = t * TILE;
        #pragma unroll
        for (int v = 0; v < 32; v++) {
            int i = v * 256 + tid;
            int r = i >> 7, k = i & 127;
            int node = min(n0g + r, NN - 1);
            pf[v] = (k < HD) ? h[(size_t)node * HD + k]
                             : g_agg[(size_t)node * HD + (k - HD)];
        }
    }

    for (; t < numTiles; t += gridDim.x) {
        const int n0g = t * TILE;
        __syncthreads();

        #pragma unroll
        for (int v = 0; v < 32; v++) {
            int i = v * 256 + tid;
            int r = i >> 7, k = i & 127;
            sU[r * MHP + k] = f2tf(pf[v]);
        }
        __syncthreads();

        int tn = t + gridDim.x;
        if (tn < numTiles) {
            const int nn0 = tn * TILE;
            #pragma unroll
            for (int v = 0; v < 32; v++) {
                int i = v * 256 + tid;
                int r = i >> 7, k = i & 127;
                int node = min(nn0 + r, NN - 1);
                pf[v] = (k < HD) ? h[(size_t)node * HD + k]
                                 : g_agg[(size_t)node * HD + (k - HD)];
            }
        }

        float c1[2][4][4];
        #pragma unroll
        for (int i = 0; i < 2; i++)
            #pragma unroll
            for (int j = 0; j < 4; j++)
                #pragma unroll
                for (int q = 0; q < 4; q++) c1[i][j][q] = 0.f;

        for (int k = 0; k < MH; k += 8) {
            uint32_t a[2][4];
            #pragma unroll
            for (int i = 0; i < 2; i++) {
                int row = mh * 32 + 16 * i + lq;
                a[i][0] = __float_as_uint(sU[row * MHP + k + lr]);
                a[i][1] = __float_as_uint(sU[(row + 8) * MHP + k + lr]);
                a[i][2] = __float_as_uint(sU[row * MHP + k + 4 + lr]);
                a[i][3] = __float_as_uint(sU[(row + 8) * MHP + k + 4 + lr]);
            }
            #pragma unroll
            for (int j = 0; j < 4; j++) {
                int n0 = nq * 32 + 8 * j;
                int cs = (n0 + lq) ^ (lr << 3);
                uint32_t b0 = __float_as_uint(sW1[(k + lr) * MH + cs]);
                uint32_t b1 = __float_as_uint(sW1[(k + 4 + lr) * MH + cs]);
                mma_tf32(c1[0][j], a[0], b0, b1);
                mma_tf32(c1[1][j], a[1], b0, b1);
            }
        }

        #pragma unroll
        for (int i = 0; i < 2; i++) {
            #pragma unroll
            for (int j = 0; j < 4; j++) {
                int row = mh * 32 + 16 * i + lq;
                int col = nq * 32 + 8 * j + 2 * lr;
                uint2 v0, v1;
                v0.x = __float_as_uint(f2tf(fmaxf(c1[i][j][0] + b1p[j].x, 0.f)));
                v0.y = __float_as_uint(f2tf(fmaxf(c1[i][j][1] + b1p[j].y, 0.f)));
                v1.x = __float_as_uint(f2tf(fmaxf(c1[i][j][2] + b1p[j].x, 0.f)));
                v1.y = __float_as_uint(f2tf(fmaxf(c1[i][j][3] + b1p[j].y, 0.f)));
                *(uint2*)&sH[row * MHP + col]       = v0;
                *(uint2*)&sH[(row + 8) * MHP + col] = v1;
            }
        }
        __syncthreads();

        float c2[4][4];
        #pragma unroll
        for (int j = 0; j < 4; j++)
            #pragma unroll
            for (int q = 0; q < 4; q++) c2[j][q] = 0.f;

        const int m0 = mq * 16;
        for (int k = 0; k < MH; k += 8) {
            uint32_t a[4];
            int row = m0 + lq;
            a[0] = __float_as_uint(sH[row * MHP + k + lr]);
            a[1] = __float_as_uint(sH[(row + 8) * MHP + k + lr]);
            a[2] = __float_as_uint(sH[row * MHP + k + 4 + lr]);
            a[3] = __float_as_uint(sH[(row + 8) * MHP + k + 4 + lr]);
            #pragma unroll
            for (int j = 0; j < 4; j++) {
                int n0 = nh * 32 + 8 * j;
                int cs = (n0 + lq) ^ (lr << 3);
                uint32_t b0 = __float_as_uint(sW2[(k + lr) * HD + cs]);
                uint32_t b1 = __float_as_uint(sW2[(k + 4 + lr) * HD + cs]);
                mma_tf32(c2[j], a, b0, b1);
            }
        }

        {
            int r0 = m0 + lq;
            int r1 = r0 + 8;
            int g0 = n0g + r0, g1 = n0g + r1;
            #pragma unroll
            for (int j = 0; j < 4; j++) {
                int col = nh * 32 + 8 * j + 2 * lr;
                if (g0 < NN) {
                    float2 hv = *(const float2*)&h[(size_t)g0 * HD + col];
                    sO[r0 * 65 + col]     = c2[j][0] + b2p[j].x + hv.x;
                    sO[r0 * 65 + col + 1] = c2[j][1] + b2p[j].y + hv.y;
                }
                if (g1 < NN) {
                    float2 hv = *(const float2*)&h[(size_t)g1 * HD + col];
                    sO[r1 * 65 + col]     = c2[j][2] + b2p[j].x + hv.x;
                    sO[r1 * 65 + col + 1] = c2[j][3] + b2p[j].y + hv.y;
                }
            }
        }
        __syncthreads();

        if (tid < TILE) {
            float s = 0.f, s2 = 0.f;
            #pragma unroll 8
            for (int c = 0; c < HD; c++) {
                float v = sO[tid * 65 + c];
                s += v;
                s2 = fmaf(v, v, s2);
            }
            float mu  = s * (1.f / HD);
            float var = fmaxf(s2 * (1.f / HD) - mu * mu, 0.f);
            sMu[tid] = mu;
            sRs[tid] = rsqrtf(var + 1e-5f);
        }
        __syncthreads();

        for (int i = tid; i < TILE * HD; i += 256) {
            int r = i >> 6;
            int c = i & 63;
            int node = n0g + r;
            if (node < NN)
                out[(size_t)node * HD + c] =
                    (sO[r * 65 + c] - sMu[r]) * sRs[r] * sG[c] + sB[c];
        }
    }
}

// ---------------------------------------------------------------------------
extern "C" void kernel_launch(void* const* d_in, const int* in_sizes, int n_in,
                              void* d_out, int out_size)
{
    const float* h   = (const float*)d_in[0];
    const int*   ei  = (const int*)d_in[1];     // int32 (JAX default downcast)
    const float* ea  = (const float*)d_in[2];
    const float* eW1 = (const float*)d_in[3];
    const float* eb1 = (const float*)d_in[4];
    const float* eW2 = (const float*)d_in[5];
    const float* eb2 = (const float*)d_in[6];
    const float* nW1 = (const float*)d_in[7];
    const float* nb1 = (const float*)d_in[8];
    const float* nW2 = (const float*)d_in[9];
    const float* nb2 = (const float*)d_in[10];
    const float* lg  = (const float*)d_in[11];
    const float* lb  = (const float*)d_in[12];
    float*       out = (float*)d_out;

    const int smem_prep = (64 * 256 + 128 * 68) * 4;
    const int smem_edge = (8 * MH + MH * HD + ET * MHP) * 4;
    const int smem_node = (MH * MH + MH * HD + 2 * TILE * MHP + TILE * 65
                           + MH + 5 * HD + TILE) * 4;

    cudaFuncSetAttribute(prep_kernel, cudaFuncAttributeMaxDynamicSharedMemorySize, smem_prep);
    cudaFuncSetAttribute(edge_kernel, cudaFuncAttributeMaxDynamicSharedMemorySize, smem_edge);
    cudaFuncSetAttribute(node_kernel, cudaFuncAttributeMaxDynamicSharedMemorySize, smem_node);

    prep_kernel<<<148, 512, smem_prep>>>(h, eW1, eb1);
    edge_kernel<<<296, 256, smem_edge>>>(ei, ea, eW1, eW2, eb2);
    node_kernel<<<148, 256, smem_node>>>(h, nW1, nb1, nW2, nb2, lg, lb, out);
}

// round 12
// speedup vs baseline: 1.1833x; 1.0550x over previous
#include <cuda_runtime.h>
#include <cstdint>

#define NN    50000
#define NE    800000
#define HD    64
#define MH    128
#define MHP   132    // padded stride (mod 32 == 4 -> conflict-free A-frags)
#define ET    64     // edge tile

// scratch
__device__ float g_agg[(size_t)NN * HD];
__device__ float g_Pcat[(size_t)NN * 256];   // [ h@W_src | h@W_dst + eb1 ]

__device__ __forceinline__ float f2tf(float f) {
    uint32_t u;
    asm("cvt.rna.tf32.f32 %0, %1;" : "=r"(u) : "f"(f));
    return __uint_as_float(u);
}

__device__ __forceinline__ void mma_tf32(float c[4], const uint32_t a[4],
                                         uint32_t b0, uint32_t b1) {
    asm volatile(
        "mma.sync.aligned.m16n8k8.row.col.f32.tf32.tf32.f32 "
        "{%0,%1,%2,%3},{%4,%5,%6,%7},{%8,%9},{%0,%1,%2,%3};"
        : "+f"(c[0]), "+f"(c[1]), "+f"(c[2]), "+f"(c[3])
        : "r"(a[0]), "r"(a[1]), "r"(a[2]), "r"(a[3]), "r"(b0), "r"(b1));
}

// ---------------------------------------------------------------------------
// prep (persistent): Pcat[n,0:128] = h@W_src ; Pcat[n,128:256] = h@W_dst + eb1
// Also zeroes g_agg rows. 148 blocks x 512 threads, weights loaded ONCE.
// ---------------------------------------------------------------------------
__global__ __launch_bounds__(512, 1)
void prep_kernel(const float* __restrict__ h, const float* __restrict__ eW1,
                 const float* __restrict__ eb1)
{
    extern __shared__ float sm[];
    float* sW = sm;             // 64 x 256, col-swizzled
    float* sA = sW + 64 * 256;  // 128 x 68

    const int tid  = threadIdx.x;
    const int lane = tid & 31;
    const int w    = tid >> 5;
    const int lq   = lane >> 2;
    const int lr   = lane & 3;

    for (int i = tid; i < 64 * 256; i += 512) {
        int k = i >> 8, c = i & 255;
        float v = (c < MH) ? eW1[k * MH + c] : eW1[(64 + k) * MH + (c - MH)];
        sW[k * 256 + (c ^ ((k & 3) << 3))] = f2tf(v);
    }

    const int mh = w >> 2, nc = w & 3;   // 4 (m32) x 4 (n64)
    const int numTiles = (NN + 127) / 128;   // 391

    for (int tile = blockIdx.x; tile < numTiles; tile += gridDim.x) {
        const int n0g = tile * 128;
        __syncthreads();

        for (int i = tid; i < 128 * 16; i += 512) {
            int r = i >> 4, c4 = i & 15;
            int node = n0g + r;
            if (node < NN)
                reinterpret_cast<float4*>(g_agg)[(size_t)node * 16 + c4] =
                    make_float4(0.f, 0.f, 0.f, 0.f);
        }
        for (int i = tid; i < 128 * 64; i += 512) {
            int r = i >> 6, c = i & 63;
            int node = min(n0g + r, NN - 1);
            sA[r * 68 + c] = f2tf(h[(size_t)node * HD + c]);
        }
        __syncthreads();

        float acc[2][8][4];
        #pragma unroll
        for (int i = 0; i < 2; i++)
            #pragma unroll
            for (int j = 0; j < 8; j++)
                #pragma unroll
                for (int q = 0; q < 4; q++) acc[i][j][q] = 0.f;

        for (int k = 0; k < 64; k += 8) {
            uint32_t a[2][4];
            #pragma unroll
            for (int i = 0; i < 2; i++) {
                int row = mh * 32 + 16 * i + lq;
                a[i][0] = __float_as_uint(sA[row * 68 + k + lr]);
                a[i][1] = __float_as_uint(sA[(row + 8) * 68 + k + lr]);
                a[i][2] = __float_as_uint(sA[row * 68 + k + 4 + lr]);
                a[i][3] = __float_as_uint(sA[(row + 8) * 68 + k + 4 + lr]);
            }
            #pragma unroll
            for (int j = 0; j < 8; j++) {
                int n0 = nc * 64 + 8 * j;
                int cs = (n0 + lq) ^ (lr << 3);
                uint32_t b0 = __float_as_uint(sW[(k + lr) * 256 + cs]);
                uint32_t b1 = __float_as_uint(sW[(k + 4 + lr) * 256 + cs]);
                mma_tf32(acc[0][j], a[0], b0, b1);
                mma_tf32(acc[1][j], a[1], b0, b1);
            }
        }

        #pragma unroll
        for (int i = 0; i < 2; i++) {
            int r0 = mh * 32 + 16 * i + lq;
            int g0 = n0g + r0, g1 = g0 + 8;
            #pragma unroll
            for (int j = 0; j < 8; j++) {
                int col = nc * 64 + 8 * j + 2 * lr;
                float bx = 0.f, by = 0.f;
                if (col >= MH) {
                    bx = eb1[col - MH];
                    by = eb1[col - MH + 1];
                }
                if (g0 < NN)
                    *(float2*)&g_Pcat[(size_t)g0 * 256 + col] =
                        make_float2(acc[i][j][0] + bx, acc[i][j][1] + by);
                if (g1 < NN)
                    *(float2*)&g_Pcat[(size_t)g1 * 256 + col] =
                        make_float2(acc[i][j][2] + bx, acc[i][j][3] + by);
            }
        }
    }
}

// ---------------------------------------------------------------------------
// Edge kernel v6: as R11, but phase-2 active warps chosen per m-half so the
// 4 active warps land on 4 DISTINCT SMSPs: mh0 -> nq<2 (warps 0,1),
// mh1 -> nq>=2 (warps 6,7). Output column base is (nq&1)*32 either way.
// ---------------------------------------------------------------------------
__global__ __launch_bounds__(256, 2)
void edge_kernel(const int* __restrict__ ei,
                 const float* __restrict__ ea,
                 const float* __restrict__ eW1,
                 const float* __restrict__ eW2, const float* __restrict__ eb2)
{
    extern __shared__ float sm[];
    float* sWea = sm;                 // 8 x 128, col-swizzled
    float* sW2  = sWea + 8 * MH;      // 128 x 64, col-swizzled
    float* sH   = sW2 + MH * HD;      // 64 x 132

    const int tid  = threadIdx.x;
    const int lane = tid & 31;
    const int w    = tid >> 5;
    const int lq   = lane >> 2;
    const int lr   = lane & 3;
    const int mh   = w >> 2;   // 0..1 -> m32 half
    const int nq   = w & 3;    // 0..3 -> n32 (phase1)
    const int barid = 1 + mh;
    // phase-2 active set spread across SMSPs: warps {0,1,6,7}
    const bool p2act = (mh == 0) ? (nq < 2) : (nq >= 2);
    const int  nn    = nq & 1;   // phase-2 n32 block index

    for (int i = tid; i < 8 * MH; i += 256) {
        int k = i >> 7, c = i & 127;
        sWea[k * MH + (c ^ ((k & 3) << 3))] = f2tf(eW1[(2 * HD + k) * MH + c]);
    }
    for (int i = tid; i < MH * HD; i += 256) {
        int r = i >> 6, n = i & 63;
        sW2[r * HD + (n ^ ((r & 3) << 3))] = f2tf(eW2[i]);
    }
    __syncthreads();

    float2 b2p[4];
    #pragma unroll
    for (int j = 0; j < 4; j++)
        b2p[j] = *(const float2*)&eb2[nn * 32 + 8 * j + 2 * lr];

    int rofs[4];
    #pragma unroll
    for (int q = 0; q < 4; q++)
        rofs[q] = mh * 32 + 16 * (q >> 1) + 8 * (q & 1) + lq;

    const int numTiles = NE / ET;   // 12500
    const int G = gridDim.x;

    // prefetch first tile into registers
    int nS[4], nD[4];
    float nA[8];
    int t = blockIdx.x;
    if (t < numTiles) {
        const int e0 = t * ET;
        #pragma unroll
        for (int q = 0; q < 4; q++) {
            nS[q] = ei[e0 + rofs[q]];
            nD[q] = ei[NE + e0 + rofs[q]];
        }
        #pragma unroll
        for (int i = 0; i < 2; i++) {
            nA[4 * i + 0] = ea[(size_t)(e0 + rofs[2 * i])     * 8 + lr];
            nA[4 * i + 1] = ea[(size_t)(e0 + rofs[2 * i + 1]) * 8 + lr];
            nA[4 * i + 2] = ea[(size_t)(e0 + rofs[2 * i])     * 8 + 4 + lr];
            nA[4 * i + 3] = ea[(size_t)(e0 + rofs[2 * i + 1]) * 8 + 4 + lr];
        }
    }

    for (; t < numTiles; t += G) {
        int cS[4], cD[4];
        uint32_t af[2][4];
        #pragma unroll
        for (int q = 0; q < 4; q++) {
            cS[q] = min(max(nS[q], 0), NN - 1);
            cD[q] = min(max(nD[q], 0), NN - 1);
        }
        #pragma unroll
        for (int i = 0; i < 2; i++)
            #pragma unroll
            for (int q = 0; q < 4; q++)
                af[i][q] = __float_as_uint(f2tf(nA[4 * i + q]));

        int tn = t + G;
        if (tn < numTiles) {
            const int en = tn * ET;
            #pragma unroll
            for (int q = 0; q < 4; q++) {
                nS[q] = ei[en + rofs[q]];
                nD[q] = ei[NE + en + rofs[q]];
            }
            #pragma unroll
            for (int i = 0; i < 2; i++) {
                nA[4 * i + 0] = ea[(size_t)(en + rofs[2 * i])     * 8 + lr];
                nA[4 * i + 1] = ea[(size_t)(en + rofs[2 * i + 1]) * 8 + lr];
                nA[4 * i + 2] = ea[(size_t)(en + rofs[2 * i])     * 8 + 4 + lr];
                nA[4 * i + 3] = ea[(size_t)(en + rofs[2 * i + 1]) * 8 + 4 + lr];
            }
        }

        // ---- phase 1: [64,8] @ [8,128] from registers (all 8 warps) ----
        float c1[2][4][4];
        #pragma unroll
        for (int i = 0; i < 2; i++)
            #pragma unroll
            for (int j = 0; j < 4; j++)
                #pragma unroll
                for (int q = 0; q < 4; q++) c1[i][j][q] = 0.f;

        #pragma unroll
        for (int j = 0; j < 4; j++) {
            int n0 = nq * 32 + 8 * j;
            int cs = (n0 + lq) ^ (lr << 3);
            uint32_t b0 = __float_as_uint(sWea[lr * MH + cs]);
            uint32_t b1 = __float_as_uint(sWea[(4 + lr) * MH + cs]);
            mma_tf32(c1[0][j], af[0], b0, b1);
            mma_tf32(c1[1][j], af[1], b0, b1);
        }

        // gathered Pcat (bias pre-folded), relu -> sH
        #pragma unroll
        for (int i = 0; i < 2; i++) {
            int r0 = rofs[2 * i];
            int r1 = rofs[2 * i + 1];
            const float* ps0 = g_Pcat + (size_t)cS[2 * i] * 256;
            const float* pd0 = g_Pcat + (size_t)cD[2 * i] * 256 + MH;
            const float* ps1 = g_Pcat + (size_t)cS[2 * i + 1] * 256;
            const float* pd1 = g_Pcat + (size_t)cD[2 * i + 1] * 256 + MH;
            #pragma unroll
            for (int j = 0; j < 4; j++) {
                int col = nq * 32 + 8 * j + 2 * lr;
                float2 s0 = *(const float2*)&ps0[col];
                float2 d0 = *(const float2*)&pd0[col];
                float2 s1 = *(const float2*)&ps1[col];
                float2 d1 = *(const float2*)&pd1[col];
                uint2 v0, v1;
                v0.x = __float_as_uint(f2tf(fmaxf(c1[i][j][0] + s0.x + d0.x, 0.f)));
                v0.y = __float_as_uint(f2tf(fmaxf(c1[i][j][1] + s0.y + d0.y, 0.f)));
                v1.x = __float_as_uint(f2tf(fmaxf(c1[i][j][2] + s1.x + d1.x, 0.f)));
                v1.y = __float_as_uint(f2tf(fmaxf(c1[i][j][3] + s1.y + d1.y, 0.f)));
                *(uint2*)&sH[r0 * MHP + col] = v0;
                *(uint2*)&sH[r1 * MHP + col] = v1;
            }
        }

        // half-block barrier: this m-half's sH writes visible to its warps
        asm volatile("bar.sync %0, 128;" :: "r"(barid) : "memory");

        // ---- phase 2: [32,128] @ [128,32] per active warp (SMSP-spread) ----
        float c2[2][4][4];
        if (p2act) {
            #pragma unroll
            for (int i = 0; i < 2; i++)
                #pragma unroll
                for (int j = 0; j < 4; j++)
                    #pragma unroll
                    for (int q = 0; q < 4; q++) c2[i][j][q] = 0.f;

            for (int k = 0; k < MH; k += 8) {
                uint32_t a[2][4];
                #pragma unroll
                for (int i = 0; i < 2; i++) {
                    int row = rofs[2 * i];
                    a[i][0] = __float_as_uint(sH[row * MHP + k + lr]);
                    a[i][1] = __float_as_uint(sH[(row + 8) * MHP + k + lr]);
                    a[i][2] = __float_as_uint(sH[row * MHP + k + 4 + lr]);
                    a[i][3] = __float_as_uint(sH[(row + 8) * MHP + k + 4 + lr]);
                }
                #pragma unroll
                for (int j = 0; j < 4; j++) {
                    int n0 = nn * 32 + 8 * j;
                    int cs = (n0 + lq) ^ (lr << 3);
                    uint32_t b0 = __float_as_uint(sW2[(k + lr) * HD + cs]);
                    uint32_t b1 = __float_as_uint(sW2[(k + 4 + lr) * HD + cs]);
                    mma_tf32(c2[0][j], a[0], b0, b1);
                    mma_tf32(c2[1][j], a[1], b0, b1);
                }
            }
        }

        // half-block barrier: sH reads done before next tile overwrites
        asm volatile("bar.sync %0, 128;" :: "r"(barid) : "memory");

        // scatter-add (active warps only; after barrier -> overlaps next tile)
        if (p2act) {
            #pragma unroll
            for (int i = 0; i < 2; i++) {
                int d0 = cD[2 * i], d1 = cD[2 * i + 1];
                #pragma unroll
                for (int j = 0; j < 4; j++) {
                    float u0 = c2[i][j][0] + b2p[j].x;
                    float u1 = c2[i][j][1] + b2p[j].y;
                    float u2 = c2[i][j][2] + b2p[j].x;
                    float u3 = c2[i][j][3] + b2p[j].y;
                    float w0 = __shfl_xor_sync(0xffffffffu, u0, 1);
                    float w1 = __shfl_xor_sync(0xffffffffu, u1, 1);
                    float w2 = __shfl_xor_sync(0xffffffffu, u2, 1);
                    float w3 = __shfl_xor_sync(0xffffffffu, u3, 1);
                    if (!(lr & 1)) {
                        int col = nn * 32 + 8 * j + (lr & 2) * 2;
                        float* p0 = g_agg + (size_t)d0 * HD + col;
                        float* p1 = g_agg + (size_t)d1 * HD + col;
                        asm volatile("red.global.add.v4.f32 [%0], {%1, %2, %3, %4};"
                                     :: "l"(p0), "f"(u0), "f"(u1), "f"(w0), "f"(w1)
                                     : "memory");
                        asm volatile("red.global.add.v4.f32 [%0], {%1, %2, %3, %4};"
                                     :: "l"(p1), "f"(u2), "f"(u3), "f"(w2), "f"(w3)
                                     : "memory");
                    }
                }
            }
        }
    }
}

// ---------------------------------------------------------------------------
// Node kernel: tf32 MMA, 64 nodes/tile, 256 threads, next-tile reg prefetch.
// ---------------------------------------------------------------------------
#define TILE 64
__global__ __launch_bounds__(256, 1)
void node_kernel(const float* __restrict__ h,
                 const float* __restrict__ nW1, const float* __restrict__ nb1,
                 const float* __restrict__ nW2, const float* __restrict__ nb2,
                 const float* __restrict__ lg,  const float* __restrict__ lb,
                 float* __restrict__ out)
{
    extern __shared__ float sm[];
    float* sW1 = sm;
    float* sW2 = sW1 + MH * MH;
    float* sU  = sW2 + MH * HD;
    float* sH  = sU  + TILE * MHP;
    float* sO  = sH  + TILE * MHP;
    float* sB1 = sO  + TILE * 65;
    float* sB2 = sB1 + MH;
    float* sG  = sB2 + HD;
    float* sB  = sG  + HD;
    float* sMu = sB  + HD;
    float* sRs = sMu + TILE;

    const int tid  = threadIdx.x;
    const int lane = tid & 31;
    const int w    = tid >> 5;
    const int lq   = lane >> 2;
    const int lr   = lane & 3;

    for (int i = tid; i < MH * MH; i += 256) {
        int r = i >> 7, n = i & 127;
        sW1[r * MH + (n ^ ((r & 3) << 3))] = f2tf(nW1[i]);
    }
    for (int i = tid; i < MH * HD; i += 256) {
        int r = i >> 6, n = i & 63;
        sW2[r * HD + (n ^ ((r & 3) << 3))] = f2tf(nW2[i]);
    }
    for (int i = tid; i < MH; i += 256) sB1[i] = nb1[i];
    if (tid < HD) { sB2[tid] = nb2[tid]; sG[tid] = lg[tid]; sB[tid] = lb[tid]; }
    __syncthreads();

    const int mh = w >> 2, nq = w & 3;
    const int mq = w & 3,  nh = w >> 2;

    float2 b1p[4], b2p[4];
    #pragma unroll
    for (int j = 0; j < 4; j++) {
        b1p[j] = *(const float2*)&sB1[nq * 32 + 8 * j + 2 * lr];
        b2p[j] = *(const float2*)&sB2[nh * 32 + 8 * j + 2 * lr];
    }

    const int numTiles = (NN + TILE - 1) / TILE;

    float pf[32];
    int t = blockIdx.x;
    if (t < numTiles) {
        const int n0g = t * TILE;
        #pragma unroll
        for (int v = 0; v < 32; v++) {
            int i = v * 256 + tid;
            int r = i >> 7, k = i & 127;
            int node = min(n0g + r, NN - 1);
            pf[v] = (k < HD) ? h[(size_t)node * HD + k]
                             : g_agg[(size_t)node * HD + (k - HD)];
        }
    }

    for (; t < numTiles; t += gridDim.x) {
        const int n0g = t * TILE;
        __syncthreads();

        #pragma unroll
        for (int v = 0; v < 32; v++) {
            int i = v * 256 + tid;
            int r = i >> 7, k = i & 127;
            sU[r * MHP + k] = f2tf(pf[v]);
        }
        __syncthreads();

        int tn = t + gridDim.x;
        if (tn < numTiles) {
            const int nn0 = tn * TILE;
            #pragma unroll
            for (int v = 0; v < 32; v++) {
                int i = v * 256 + tid;
                int r = i >> 7, k = i & 127;
                int node = min(nn0 + r, NN - 1);
                pf[v] = (k < HD) ? h[(size_t)node * HD + k]
                                 : g_agg[(size_t)node * HD + (k - HD)];
            }
        }

        float c1[2][4][4];
        #pragma unroll
        for (int i = 0; i < 2; i++)
            #pragma unroll
            for (int j = 0; j < 4; j++)
                #pragma unroll
                for (int q = 0; q < 4; q++) c1[i][j][q] = 0.f;

        for (int k = 0; k < MH; k += 8) {
            uint32_t a[2][4];
            #pragma unroll
            for (int i = 0; i < 2; i++) {
                int row = mh * 32 + 16 * i + lq;
                a[i][0] = __float_as_uint(sU[row * MHP + k + lr]);
                a[i][1] = __float_as_uint(sU[(row + 8) * MHP + k + lr]);
                a[i][2] = __float_as_uint(sU[row * MHP + k + 4 + lr]);
                a[i][3] = __float_as_uint(sU[(row + 8) * MHP + k + 4 + lr]);
            }
            #pragma unroll
            for (int j = 0; j < 4; j++) {
                int n0 = nq * 32 + 8 * j;
                int cs = (n0 + lq) ^ (lr << 3);
                uint32_t b0 = __float_as_uint(sW1[(k + lr) * MH + cs]);
                uint32_t b1 = __float_as_uint(sW1[(k + 4 + lr) * MH + cs]);
                mma_tf32(c1[0][j], a[0], b0, b1);
                mma_tf32(c1[1][j], a[1], b0, b1);
            }
        }

        #pragma unroll
        for (int i = 0; i < 2; i++) {
            #pragma unroll
            for (int j = 0; j < 4; j++) {
                int row = mh * 32 + 16 * i + lq;
                int col = nq * 32 + 8 * j + 2 * lr;
                uint2 v0, v1;
                v0.x = __float_as_uint(f2tf(fmaxf(c1[i][j][0] + b1p[j].x, 0.f)));
                v0.y = __float_as_uint(f2tf(fmaxf(c1[i][j][1] + b1p[j].y, 0.f)));
                v1.x = __float_as_uint(f2tf(fmaxf(c1[i][j][2] + b1p[j].x, 0.f)));
                v1.y = __float_as_uint(f2tf(fmaxf(c1[i][j][3] + b1p[j].y, 0.f)));
                *(uint2*)&sH[row * MHP + col]       = v0;
                *(uint2*)&sH[(row + 8) * MHP + col] = v1;
            }
        }
        __syncthreads();

        float c2[4][4];
        #pragma unroll
        for (int j = 0; j < 4; j++)
            #pragma unroll
            for (int q = 0; q < 4; q++) c2[j][q] = 0.f;

        const int m0 = mq * 16;
        for (int k = 0; k < MH; k += 8) {
            uint32_t a[4];
            int row = m0 + lq;
            a[0] = __float_as_uint(sH[row * MHP + k + lr]);
            a[1] = __float_as_uint(sH[(row + 8) * MHP + k + lr]);
            a[2] = __float_as_uint(sH[row * MHP + k + 4 + lr]);
            a[3] = __float_as_uint(sH[(row + 8) * MHP + k + 4 + lr]);
            #pragma unroll
            for (int j = 0; j < 4; j++) {
                int n0 = nh * 32 + 8 * j;
                int cs = (n0 + lq) ^ (lr << 3);
                uint32_t b0 = __float_as_uint(sW2[(k + lr) * HD + cs]);
                uint32_t b1 = __float_as_uint(sW2[(k + 4 + lr) * HD + cs]);
                mma_tf32(c2[j], a, b0, b1);
            }
        }

        {
            int r0 = m0 + lq;
            int r1 = r0 + 8;
            int g0 = n0g + r0, g1 = n0g + r1;
            #pragma unroll
            for (int j = 0; j < 4; j++) {
                int col = nh * 32 + 8 * j + 2 * lr;
                if (g0 < NN) {
                    float2 hv = *(const float2*)&h[(size_t)g0 * HD + col];
                    sO[r0 * 65 + col]     = c2[j][0] + b2p[j].x + hv.x;
                    sO[r0 * 65 + col + 1] = c2[j][1] + b2p[j].y + hv.y;
                }
                if (g1 < NN) {
                    float2 hv = *(const float2*)&h[(size_t)g1 * HD + col];
                    sO[r1 * 65 + col]     = c2[j][2] + b2p[j].x + hv.x;
                    sO[r1 * 65 + col + 1] = c2[j][3] + b2p[j].y + hv.y;
                }
            }
        }
        __syncthreads();

        if (tid < TILE) {
            float s = 0.f, s2 = 0.f;
            #pragma unroll 8
            for (int c = 0; c < HD; c++) {
                float v = sO[tid * 65 + c];
                s += v;
                s2 = fmaf(v, v, s2);
            }
            float mu  = s * (1.f / HD);
            float var = fmaxf(s2 * (1.f / HD) - mu * mu, 0.f);
            sMu[tid] = mu;
            sRs[tid] = rsqrtf(var + 1e-5f);
        }
        __syncthreads();

        for (int i = tid; i < TILE * HD; i += 256) {
            int r = i >> 6;
            int c = i & 63;
            int node = n0g + r;
            if (node < NN)
                out[(size_t)node * HD + c] =
                    (sO[r * 65 + c] - sMu[r]) * sRs[r] * sG[c] + sB[c];
        }
    }
}

// ---------------------------------------------------------------------------
extern "C" void kernel_launch(void* const* d_in, const int* in_sizes, int n_in,
                              void* d_out, int out_size)
{
    const float* h   = (const float*)d_in[0];
    const int*   ei  = (const int*)d_in[1];     // int32 (JAX default downcast)
    const float* ea  = (const float*)d_in[2];
    const float* eW1 = (const float*)d_in[3];
    const float* eb1 = (const float*)d_in[4];
    const float* eW2 = (const float*)d_in[5];
    const float* eb2 = (const float*)d_in[6];
    const float* nW1 = (const float*)d_in[7];
    const float* nb1 = (const float*)d_in[8];
    const float* nW2 = (const float*)d_in[9];
    const float* nb2 = (const float*)d_in[10];
    const float* lg  = (const float*)d_in[11];
    const float* lb  = (const float*)d_in[12];
    float*       out = (float*)d_out;

    const int smem_prep = (64 * 256 + 128 * 68) * 4;
    const int smem_edge = (8 * MH + MH * HD + ET * MHP) * 4;
    const int smem_node = (MH * MH + MH * HD + 2 * TILE * MHP + TILE * 65
                           + MH + 5 * HD + TILE) * 4;

    cudaFuncSetAttribute(prep_kernel, cudaFuncAttributeMaxDynamicSharedMemorySize, smem_prep);
    cudaFuncSetAttribute(edge_kernel, cudaFuncAttributeMaxDynamicSharedMemorySize, smem_edge);
    cudaFuncSetAttribute(node_kernel, cudaFuncAttributeMaxDynamicSharedMemorySize, smem_node);

    prep_kernel<<<148, 512, smem_prep>>>(h, eW1, eb1);
    edge_kernel<<<296, 256, smem_edge>>>(ei, ea, eW1, eW2, eb2);
    node_kernel<<<148, 256, smem_node>>>(h, nW1, nb1, nW2, nb2, lg, lb, out);
}

// round 13
// speedup vs baseline: 1.1872x; 1.0033x over previous
#include <cuda_runtime.h>
#include <cstdint>

#define NN    50000
#define NE    800000
#define HD    64
#define MH    128
#define MHP   132    // padded stride (mod 32 == 4 -> conflict-free A-frags)
#define ET    64     // edge tile

// scratch
__device__ float g_agg[(size_t)NN * HD];
__device__ float g_Pcat[(size_t)NN * 256];   // [ h@W_src | h@W_dst + eb1 ]

__device__ __forceinline__ float f2tf(float f) {
    uint32_t u;
    asm("cvt.rna.tf32.f32 %0, %1;" : "=r"(u) : "f"(f));
    return __uint_as_float(u);
}

__device__ __forceinline__ void mma_tf32(float c[4], const uint32_t a[4],
                                         uint32_t b0, uint32_t b1) {
    asm volatile(
        "mma.sync.aligned.m16n8k8.row.col.f32.tf32.tf32.f32 "
        "{%0,%1,%2,%3},{%4,%5,%6,%7},{%8,%9},{%0,%1,%2,%3};"
        : "+f"(c[0]), "+f"(c[1]), "+f"(c[2]), "+f"(c[3])
        : "r"(a[0]), "r"(a[1]), "r"(a[2]), "r"(a[3]), "r"(b0), "r"(b1));
}

// ---------------------------------------------------------------------------
// prep (persistent): Pcat[n,0:128] = h@W_src ; Pcat[n,128:256] = h@W_dst + eb1
// Also zeroes g_agg rows. 148 blocks x 512 threads, weights loaded ONCE.
// ---------------------------------------------------------------------------
__global__ __launch_bounds__(512, 1)
void prep_kernel(const float* __restrict__ h, const float* __restrict__ eW1,
                 const float* __restrict__ eb1)
{
    extern __shared__ float sm[];
    float* sW = sm;             // 64 x 256, col-swizzled
    float* sA = sW + 64 * 256;  // 128 x 68

    const int tid  = threadIdx.x;
    const int lane = tid & 31;
    const int w    = tid >> 5;
    const int lq   = lane >> 2;
    const int lr   = lane & 3;

    for (int i = tid; i < 64 * 256; i += 512) {
        int k = i >> 8, c = i & 255;
        float v = (c < MH) ? eW1[k * MH + c] : eW1[(64 + k) * MH + (c - MH)];
        sW[k * 256 + (c ^ ((k & 3) << 3))] = f2tf(v);
    }

    const int mh = w >> 2, nc = w & 3;   // 4 (m32) x 4 (n64)
    const int numTiles = (NN + 127) / 128;   // 391

    for (int tile = blockIdx.x; tile < numTiles; tile += gridDim.x) {
        const int n0g = tile * 128;
        __syncthreads();

        for (int i = tid; i < 128 * 16; i += 512) {
            int r = i >> 4, c4 = i & 15;
            int node = n0g + r;
            if (node < NN)
                reinterpret_cast<float4*>(g_agg)[(size_t)node * 16 + c4] =
                    make_float4(0.f, 0.f, 0.f, 0.f);
        }
        for (int i = tid; i < 128 * 64; i += 512) {
            int r = i >> 6, c = i & 63;
            int node = min(n0g + r, NN - 1);
            sA[r * 68 + c] = f2tf(h[(size_t)node * HD + c]);
        }
        __syncthreads();

        float acc[2][8][4];
        #pragma unroll
        for (int i = 0; i < 2; i++)
            #pragma unroll
            for (int j = 0; j < 8; j++)
                #pragma unroll
                for (int q = 0; q < 4; q++) acc[i][j][q] = 0.f;

        for (int k = 0; k < 64; k += 8) {
            uint32_t a[2][4];
            #pragma unroll
            for (int i = 0; i < 2; i++) {
                int row = mh * 32 + 16 * i + lq;
                a[i][0] = __float_as_uint(sA[row * 68 + k + lr]);
                a[i][1] = __float_as_uint(sA[(row + 8) * 68 + k + lr]);
                a[i][2] = __float_as_uint(sA[row * 68 + k + 4 + lr]);
                a[i][3] = __float_as_uint(sA[(row + 8) * 68 + k + 4 + lr]);
            }
            #pragma unroll
            for (int j = 0; j < 8; j++) {
                int n0 = nc * 64 + 8 * j;
                int cs = (n0 + lq) ^ (lr << 3);
                uint32_t b0 = __float_as_uint(sW[(k + lr) * 256 + cs]);
                uint32_t b1 = __float_as_uint(sW[(k + 4 + lr) * 256 + cs]);
                mma_tf32(acc[0][j], a[0], b0, b1);
                mma_tf32(acc[1][j], a[1], b0, b1);
            }
        }

        #pragma unroll
        for (int i = 0; i < 2; i++) {
            int r0 = mh * 32 + 16 * i + lq;
            int g0 = n0g + r0, g1 = g0 + 8;
            #pragma unroll
            for (int j = 0; j < 8; j++) {
                int col = nc * 64 + 8 * j + 2 * lr;
                float bx = 0.f, by = 0.f;
                if (col >= MH) {
                    bx = eb1[col - MH];
                    by = eb1[col - MH + 1];
                }
                if (g0 < NN)
                    *(float2*)&g_Pcat[(size_t)g0 * 256 + col] =
                        make_float2(acc[i][j][0] + bx, acc[i][j][1] + by);
                if (g1 < NN)
                    *(float2*)&g_Pcat[(size_t)g1 * 256 + col] =
                        make_float2(acc[i][j][2] + bx, acc[i][j][3] + by);
            }
        }
    }
}

// ---------------------------------------------------------------------------
// Edge kernel v6 (R12) + tile-invariant phase-1 B-fragment hoist.
// ---------------------------------------------------------------------------
__global__ __launch_bounds__(256, 2)
void edge_kernel(const int* __restrict__ ei,
                 const float* __restrict__ ea,
                 const float* __restrict__ eW1,
                 const float* __restrict__ eW2, const float* __restrict__ eb2)
{
    extern __shared__ float sm[];
    float* sWea = sm;                 // 8 x 128, col-swizzled
    float* sW2  = sWea + 8 * MH;      // 128 x 64, col-swizzled
    float* sH   = sW2 + MH * HD;      // 64 x 132

    const int tid  = threadIdx.x;
    const int lane = tid & 31;
    const int w    = tid >> 5;
    const int lq   = lane >> 2;
    const int lr   = lane & 3;
    const int mh   = w >> 2;
    const int nq   = w & 3;
    const int barid = 1 + mh;
    const bool p2act = (mh == 0) ? (nq < 2) : (nq >= 2);
    const int  nn    = nq & 1;

    for (int i = tid; i < 8 * MH; i += 256) {
        int k = i >> 7, c = i & 127;
        sWea[k * MH + (c ^ ((k & 3) << 3))] = f2tf(eW1[(2 * HD + k) * MH + c]);
    }
    for (int i = tid; i < MH * HD; i += 256) {
        int r = i >> 6, n = i & 63;
        sW2[r * HD + (n ^ ((r & 3) << 3))] = f2tf(eW2[i]);
    }
    __syncthreads();

    uint32_t wb0[4], wb1[4];
    #pragma unroll
    for (int j = 0; j < 4; j++) {
        int n0 = nq * 32 + 8 * j;
        int cs = (n0 + lq) ^ (lr << 3);
        wb0[j] = __float_as_uint(sWea[lr * MH + cs]);
        wb1[j] = __float_as_uint(sWea[(4 + lr) * MH + cs]);
    }

    float2 b2p[4];
    #pragma unroll
    for (int j = 0; j < 4; j++)
        b2p[j] = *(const float2*)&eb2[nn * 32 + 8 * j + 2 * lr];

    int rofs[4];
    #pragma unroll
    for (int q = 0; q < 4; q++)
        rofs[q] = mh * 32 + 16 * (q >> 1) + 8 * (q & 1) + lq;

    const int numTiles = NE / ET;
    const int G = gridDim.x;

    int nS[4], nD[4];
    float nA[8];
    int t = blockIdx.x;
    if (t < numTiles) {
        const int e0 = t * ET;
        #pragma unroll
        for (int q = 0; q < 4; q++) {
            nS[q] = ei[e0 + rofs[q]];
            nD[q] = ei[NE + e0 + rofs[q]];
        }
        #pragma unroll
        for (int i = 0; i < 2; i++) {
            nA[4 * i + 0] = ea[(size_t)(e0 + rofs[2 * i])     * 8 + lr];
            nA[4 * i + 1] = ea[(size_t)(e0 + rofs[2 * i + 1]) * 8 + lr];
            nA[4 * i + 2] = ea[(size_t)(e0 + rofs[2 * i])     * 8 + 4 + lr];
            nA[4 * i + 3] = ea[(size_t)(e0 + rofs[2 * i + 1]) * 8 + 4 + lr];
        }
    }

    for (; t < numTiles; t += G) {
        int cS[4], cD[4];
        uint32_t af[2][4];
        #pragma unroll
        for (int q = 0; q < 4; q++) {
            cS[q] = min(max(nS[q], 0), NN - 1);
            cD[q] = min(max(nD[q], 0), NN - 1);
        }
        #pragma unroll
        for (int i = 0; i < 2; i++)
            #pragma unroll
            for (int q = 0; q < 4; q++)
                af[i][q] = __float_as_uint(f2tf(nA[4 * i + q]));

        int tn = t + G;
        if (tn < numTiles) {
            const int en = tn * ET;
            #pragma unroll
            for (int q = 0; q < 4; q++) {
                nS[q] = ei[en + rofs[q]];
                nD[q] = ei[NE + en + rofs[q]];
            }
            #pragma unroll
            for (int i = 0; i < 2; i++) {
                nA[4 * i + 0] = ea[(size_t)(en + rofs[2 * i])     * 8 + lr];
                nA[4 * i + 1] = ea[(size_t)(en + rofs[2 * i + 1]) * 8 + lr];
                nA[4 * i + 2] = ea[(size_t)(en + rofs[2 * i])     * 8 + 4 + lr];
                nA[4 * i + 3] = ea[(size_t)(en + rofs[2 * i + 1]) * 8 + 4 + lr];
            }
        }

        float c1[2][4][4];
        #pragma unroll
        for (int i = 0; i < 2; i++)
            #pragma unroll
            for (int j = 0; j < 4; j++)
                #pragma unroll
                for (int q = 0; q < 4; q++) c1[i][j][q] = 0.f;

        #pragma unroll
        for (int j = 0; j < 4; j++) {
            mma_tf32(c1[0][j], af[0], wb0[j], wb1[j]);
            mma_tf32(c1[1][j], af[1], wb0[j], wb1[j]);
        }

        #pragma unroll
        for (int i = 0; i < 2; i++) {
            int r0 = rofs[2 * i];
            int r1 = rofs[2 * i + 1];
            const float* ps0 = g_Pcat + (size_t)cS[2 * i] * 256;
            const float* pd0 = g_Pcat + (size_t)cD[2 * i] * 256 + MH;
            const float* ps1 = g_Pcat + (size_t)cS[2 * i + 1] * 256;
            const float* pd1 = g_Pcat + (size_t)cD[2 * i + 1] * 256 + MH;
            #pragma unroll
            for (int j = 0; j < 4; j++) {
                int col = nq * 32 + 8 * j + 2 * lr;
                float2 s0 = *(const float2*)&ps0[col];
                float2 d0 = *(const float2*)&pd0[col];
                float2 s1 = *(const float2*)&ps1[col];
                float2 d1 = *(const float2*)&pd1[col];
                uint2 v0, v1;
                v0.x = __float_as_uint(f2tf(fmaxf(c1[i][j][0] + s0.x + d0.x, 0.f)));
                v0.y = __float_as_uint(f2tf(fmaxf(c1[i][j][1] + s0.y + d0.y, 0.f)));
                v1.x = __float_as_uint(f2tf(fmaxf(c1[i][j][2] + s1.x + d1.x, 0.f)));
                v1.y = __float_as_uint(f2tf(fmaxf(c1[i][j][3] + s1.y + d1.y, 0.f)));
                *(uint2*)&sH[r0 * MHP + col] = v0;
                *(uint2*)&sH[r1 * MHP + col] = v1;
            }
        }

        asm volatile("bar.sync %0, 128;" :: "r"(barid) : "memory");

        float c2[2][4][4];
        if (p2act) {
            #pragma unroll
            for (int i = 0; i < 2; i++)
                #pragma unroll
                for (int j = 0; j < 4; j++)
                    #pragma unroll
                    for (int q = 0; q < 4; q++) c2[i][j][q] = 0.f;

            for (int k = 0; k < MH; k += 8) {
                uint32_t a[2][4];
                #pragma unroll
                for (int i = 0; i < 2; i++) {
                    int row = rofs[2 * i];
                    a[i][0] = __float_as_uint(sH[row * MHP + k + lr]);
                    a[i][1] = __float_as_uint(sH[(row + 8) * MHP + k + lr]);
                    a[i][2] = __float_as_uint(sH[row * MHP + k + 4 + lr]);
                    a[i][3] = __float_as_uint(sH[(row + 8) * MHP + k + 4 + lr]);
                }
                #pragma unroll
                for (int j = 0; j < 4; j++) {
                    int n0 = nn * 32 + 8 * j;
                    int cs = (n0 + lq) ^ (lr << 3);
                    uint32_t b0 = __float_as_uint(sW2[(k + lr) * HD + cs]);
                    uint32_t b1 = __float_as_uint(sW2[(k + 4 + lr) * HD + cs]);
                    mma_tf32(c2[0][j], a[0], b0, b1);
                    mma_tf32(c2[1][j], a[1], b0, b1);
                }
            }
        }

        asm volatile("bar.sync %0, 128;" :: "r"(barid) : "memory");

        if (p2act) {
            #pragma unroll
            for (int i = 0; i < 2; i++) {
                int d0 = cD[2 * i], d1 = cD[2 * i + 1];
                #pragma unroll
                for (int j = 0; j < 4; j++) {
                    float u0 = c2[i][j][0] + b2p[j].x;
                    float u1 = c2[i][j][1] + b2p[j].y;
                    float u2 = c2[i][j][2] + b2p[j].x;
                    float u3 = c2[i][j][3] + b2p[j].y;
                    float w0 = __shfl_xor_sync(0xffffffffu, u0, 1);
                    float w1 = __shfl_xor_sync(0xffffffffu, u1, 1);
                    float w2 = __shfl_xor_sync(0xffffffffu, u2, 1);
                    float w3 = __shfl_xor_sync(0xffffffffu, u3, 1);
                    if (!(lr & 1)) {
                        int col = nn * 32 + 8 * j + (lr & 2) * 2;
                        float* p0 = g_agg + (size_t)d0 * HD + col;
                        float* p1 = g_agg + (size_t)d1 * HD + col;
                        asm volatile("red.global.add.v4.f32 [%0], {%1, %2, %3, %4};"
                                     :: "l"(p0), "f"(u0), "f"(u1), "f"(w0), "f"(w1)
                                     : "memory");
                        asm volatile("red.global.add.v4.f32 [%0], {%1, %2, %3, %4};"
                                     :: "l"(p1), "f"(u2), "f"(u3), "f"(w2), "f"(w3)
                                     : "memory");
                    }
                }
            }
        }
    }
}

// ---------------------------------------------------------------------------
// Node kernel v2: half-block decoupled (named half-barriers), shuffle-based
// LayerNorm stats. 256 threads, grid-stride, register prefetch.
// ---------------------------------------------------------------------------
#define TILE 64
__global__ __launch_bounds__(256, 1)
void node_kernel(const float* __restrict__ h,
                 const float* __restrict__ nW1, const float* __restrict__ nb1,
                 const float* __restrict__ nW2, const float* __restrict__ nb2,
                 const float* __restrict__ lg,  const float* __restrict__ lb,
                 float* __restrict__ out)
{
    extern __shared__ float sm[];
    float* sW1 = sm;                    // 128x128 swizzled
    float* sW2 = sW1 + MH * MH;         // 128x64 swizzled
    float* sU  = sW2 + MH * HD;         // 64 x 132
    float* sH  = sU  + TILE * MHP;      // 64 x 132
    float* sO  = sH  + TILE * MHP;      // 64 x 65
    float* sP  = sO  + TILE * 65;       // 64 x 4  (s,q per (row, ni))
    float* sB1 = sP  + TILE * 4;        // 128
    float* sB2 = sB1 + MH;              // 64
    float* sG  = sB2 + HD;              // 64
    float* sB  = sG  + HD;              // 64

    const int tid  = threadIdx.x;
    const int lane = tid & 31;
    const int w    = tid >> 5;
    const int lq   = lane >> 2;
    const int lr   = lane & 3;
    const int mh   = w >> 2;            // half: warps 0-3 / 4-7
    const int nq   = w & 3;
    const int mi   = nq >> 1;           // phase-2 m16 tile within half
    const int ni   = nq & 1;            // phase-2 n32 tile
    const int t128 = tid & 127;
    const int barid = 1 + mh;

    for (int i = tid; i < MH * MH; i += 256) {
        int r = i >> 7, n = i & 127;
        sW1[r * MH + (n ^ ((r & 3) << 3))] = f2tf(nW1[i]);
    }
    for (int i = tid; i < MH * HD; i += 256) {
        int r = i >> 6, n = i & 63;
        sW2[r * HD + (n ^ ((r & 3) << 3))] = f2tf(nW2[i]);
    }
    for (int i = tid; i < MH; i += 256) sB1[i] = nb1[i];
    if (tid < HD) { sB2[tid] = nb2[tid]; sG[tid] = lg[tid]; sB[tid] = lb[tid]; }
    __syncthreads();

    float2 b1p[4], b2p[4];
    #pragma unroll
    for (int j = 0; j < 4; j++) {
        b1p[j] = *(const float2*)&sB1[nq * 32 + 8 * j + 2 * lr];
        b2p[j] = *(const float2*)&sB2[ni * 32 + 8 * j + 2 * lr];
    }

    const int numTiles = (NN + TILE - 1) / TILE;

    // prefetch: thread owns column k=t128 of its half's 32 rows
    float pf[32];
    int t = blockIdx.x;
    if (t < numTiles) {
        const int n0g = t * TILE;
        #pragma unroll
        for (int v = 0; v < 32; v++) {
            int node = min(n0g + mh * 32 + v, NN - 1);
            pf[v] = (t128 < HD) ? h[(size_t)node * HD + t128]
                                : g_agg[(size_t)node * HD + (t128 - HD)];
        }
    }

    for (; t < numTiles; t += gridDim.x) {
        const int n0g = t * TILE;

        // commit prefetched gather -> sU (own half rows)
        #pragma unroll
        for (int v = 0; v < 32; v++)
            sU[(mh * 32 + v) * MHP + t128] = f2tf(pf[v]);

        asm volatile("bar.sync %0, 128;" :: "r"(barid) : "memory");  // (A)

        int tn = t + gridDim.x;
        if (tn < numTiles) {
            const int nn0 = tn * TILE;
            #pragma unroll
            for (int v = 0; v < 32; v++) {
                int node = min(nn0 + mh * 32 + v, NN - 1);
                pf[v] = (t128 < HD) ? h[(size_t)node * HD + t128]
                                    : g_agg[(size_t)node * HD + (t128 - HD)];
            }
        }

        // ---- phase 1: own-half rows, [32,128] @ [128,128] ----
        float c1[2][4][4];
        #pragma unroll
        for (int i = 0; i < 2; i++)
            #pragma unroll
            for (int j = 0; j < 4; j++)
                #pragma unroll
                for (int q = 0; q < 4; q++) c1[i][j][q] = 0.f;

        for (int k = 0; k < MH; k += 8) {
            uint32_t a[2][4];
            #pragma unroll
            for (int i = 0; i < 2; i++) {
                int row = mh * 32 + 16 * i + lq;
                a[i][0] = __float_as_uint(sU[row * MHP + k + lr]);
                a[i][1] = __float_as_uint(sU[(row + 8) * MHP + k + lr]);
                a[i][2] = __float_as_uint(sU[row * MHP + k + 4 + lr]);
                a[i][3] = __float_as_uint(sU[(row + 8) * MHP + k + 4 + lr]);
            }
            #pragma unroll
            for (int j = 0; j < 4; j++) {
                int n0 = nq * 32 + 8 * j;
                int cs = (n0 + lq) ^ (lr << 3);
                uint32_t b0 = __float_as_uint(sW1[(k + lr) * MH + cs]);
                uint32_t b1 = __float_as_uint(sW1[(k + 4 + lr) * MH + cs]);
                mma_tf32(c1[0][j], a[0], b0, b1);
                mma_tf32(c1[1][j], a[1], b0, b1);
            }
        }

        #pragma unroll
        for (int i = 0; i < 2; i++) {
            #pragma unroll
            for (int j = 0; j < 4; j++) {
                int row = mh * 32 + 16 * i + lq;
                int col = nq * 32 + 8 * j + 2 * lr;
                uint2 v0, v1;
                v0.x = __float_as_uint(f2tf(fmaxf(c1[i][j][0] + b1p[j].x, 0.f)));
                v0.y = __float_as_uint(f2tf(fmaxf(c1[i][j][1] + b1p[j].y, 0.f)));
                v1.x = __float_as_uint(f2tf(fmaxf(c1[i][j][2] + b1p[j].x, 0.f)));
                v1.y = __float_as_uint(f2tf(fmaxf(c1[i][j][3] + b1p[j].y, 0.f)));
                *(uint2*)&sH[row * MHP + col]       = v0;
                *(uint2*)&sH[(row + 8) * MHP + col] = v1;
            }
        }

        asm volatile("bar.sync %0, 128;" :: "r"(barid) : "memory");  // (B)

        // ---- phase 2: m16 x n32 within own half ----
        float c2[4][4];
        #pragma unroll
        for (int j = 0; j < 4; j++)
            #pragma unroll
            for (int q = 0; q < 4; q++) c2[j][q] = 0.f;

        const int m0 = mh * 32 + mi * 16;
        for (int k = 0; k < MH; k += 8) {
            uint32_t a[4];
            int row = m0 + lq;
            a[0] = __float_as_uint(sH[row * MHP + k + lr]);
            a[1] = __float_as_uint(sH[(row + 8) * MHP + k + lr]);
            a[2] = __float_as_uint(sH[row * MHP + k + 4 + lr]);
            a[3] = __float_as_uint(sH[(row + 8) * MHP + k + 4 + lr]);
            #pragma unroll
            for (int j = 0; j < 4; j++) {
                int n0 = ni * 32 + 8 * j;
                int cs = (n0 + lq) ^ (lr << 3);
                uint32_t b0 = __float_as_uint(sW2[(k + lr) * HD + cs]);
                uint32_t b1 = __float_as_uint(sW2[(k + 4 + lr) * HD + cs]);
                mma_tf32(c2[j], a, b0, b1);
            }
        }

        // epilogue: residual + bias -> sO; LN partial sums from registers
        {
            int r0 = m0 + lq;
            int r1 = r0 + 8;
            int g0 = min(n0g + r0, NN - 1);
            int g1 = min(n0g + r1, NN - 1);
            float s0 = 0.f, q0 = 0.f, s1 = 0.f, q1 = 0.f;
            #pragma unroll
            for (int j = 0; j < 4; j++) {
                int col = ni * 32 + 8 * j + 2 * lr;
                float2 h0 = *(const float2*)&h[(size_t)g0 * HD + col];
                float2 h1 = *(const float2*)&h[(size_t)g1 * HD + col];
                float x0 = c2[j][0] + b2p[j].x + h0.x;
                float x1 = c2[j][1] + b2p[j].y + h0.y;
                float x2 = c2[j][2] + b2p[j].x + h1.x;
                float x3 = c2[j][3] + b2p[j].y + h1.y;
                sO[r0 * 65 + col]     = x0;
                sO[r0 * 65 + col + 1] = x1;
                sO[r1 * 65 + col]     = x2;
                sO[r1 * 65 + col + 1] = x3;
                s0 += x0 + x1;  q0 = fmaf(x0, x0, fmaf(x1, x1, q0));
                s1 += x2 + x3;  q1 = fmaf(x2, x2, fmaf(x3, x3, q1));
            }
            s0 += __shfl_xor_sync(0xffffffffu, s0, 1);
            s0 += __shfl_xor_sync(0xffffffffu, s0, 2);
            q0 += __shfl_xor_sync(0xffffffffu, q0, 1);
            q0 += __shfl_xor_sync(0xffffffffu, q0, 2);
            s1 += __shfl_xor_sync(0xffffffffu, s1, 1);
            s1 += __shfl_xor_sync(0xffffffffu, s1, 2);
            q1 += __shfl_xor_sync(0xffffffffu, q1, 1);
            q1 += __shfl_xor_sync(0xffffffffu, q1, 2);
            if (lr == 0) {
                sP[r0 * 4 + ni * 2 + 0] = s0;
                sP[r0 * 4 + ni * 2 + 1] = q0;
                sP[r1 * 4 + ni * 2 + 0] = s1;
                sP[r1 * 4 + ni * 2 + 1] = q1;
            }
        }

        asm volatile("bar.sync %0, 128;" :: "r"(barid) : "memory");  // (C)

        // out write: thread -> one row-quarter; one rsqrt per thread
        {
            int r_l  = mh * 32 + (t128 >> 2);
            int c0   = (t128 & 3) * 16;
            int node = n0g + r_l;
            if (node < NN) {
                float s  = sP[r_l * 4 + 0] + sP[r_l * 4 + 2];
                float q  = sP[r_l * 4 + 1] + sP[r_l * 4 + 3];
                float mu = s * (1.f / HD);
                float vr = fmaxf(q * (1.f / HD) - mu * mu, 0.f);
                float rs = rsqrtf(vr + 1e-5f);
                #pragma unroll
                for (int c = 0; c < 16; c += 2) {
                    float a0 = (sO[r_l * 65 + c0 + c]     - mu) * rs * sG[c0 + c]     + sB[c0 + c];
                    float a1 = (sO[r_l * 65 + c0 + c + 1] - mu) * rs * sG[c0 + c + 1] + sB[c0 + c + 1];
                    *(float2*)&out[(size_t)node * HD + c0 + c] = make_float2(a0, a1);
                }
            }
        }

        asm volatile("bar.sync %0, 128;" :: "r"(barid) : "memory");  // (D)
    }
}

// ---------------------------------------------------------------------------
extern "C" void kernel_launch(void* const* d_in, const int* in_sizes, int n_in,
                              void* d_out, int out_size)
{
    const float* h   = (const float*)d_in[0];
    const int*   ei  = (const int*)d_in[1];     // int32 (JAX default downcast)
    const float* ea  = (const float*)d_in[2];
    const float* eW1 = (const float*)d_in[3];
    const float* eb1 = (const float*)d_in[4];
    const float* eW2 = (const float*)d_in[5];
    const float* eb2 = (const float*)d_in[6];
    const float* nW1 = (const float*)d_in[7];
    const float* nb1 = (const float*)d_in[8];
    const float* nW2 = (const float*)d_in[9];
    const float* nb2 = (const float*)d_in[10];
    const float* lg  = (const float*)d_in[11];
    const float* lb  = (const float*)d_in[12];
    float*       out = (float*)d_out;

    const int smem_prep = (64 * 256 + 128 * 68) * 4;
    const int smem_edge = (8 * MH + MH * HD + ET * MHP) * 4;
    const int smem_node = (MH * MH + MH * HD + 2 * TILE * MHP + TILE * 65
                           + TILE * 4 + MH + 3 * HD) * 4;

    cudaFuncSetAttribute(prep_kernel, cudaFuncAttributeMaxDynamicSharedMemorySize, smem_prep);
    cudaFuncSetAttribute(edge_kernel, cudaFuncAttributeMaxDynamicSharedMemorySize, smem_edge);
    cudaFuncSetAttribute(node_kernel, cudaFuncAttributeMaxDynamicSharedMemorySize, smem_node);

    prep_kernel<<<148, 512, smem_prep>>>(h, eW1, eb1);
    edge_kernel<<<296, 256, smem_edge>>>(ei, ea, eW1, eW2, eb2);
    node_kernel<<<148, 256, smem_node>>>(h, nW1, nb1, nW2, nb2, lg, lb, out);
}